// round 1
// baseline (speedup 1.0000x reference)
#include <cuda_runtime.h>

#define N_SRC 8192
#define N_TGT 16384
#define DD 64
#define HH 128
#define KN 32
#define CMAX 256

// ---- device scratch (no allocations allowed) ----
static __device__ float  g_S[N_SRC * HH];     // src_features @ W1[:64] + b1
static __device__ float4 g_spos[N_SRC];       // packed src pos + (float)batch

// ---- shared memory layout for k_main (offsets in floats) ----
#define OFF_W2   0        // 16384  (128x128 W2)
#define OFF_H1   16384    // 4096   (h1[32][128])
#define OFF_RED  20480    // 1024   (8 m-groups x 128 channels)
#define OFF_CD2  21504    // 256    (candidate d2; reused as rel[32][3])
#define OFF_CIDX 21760    // 256    (candidate idx, int)
#define OFF_SEL  22016    // 32     (selected idx, int)
#define OFF_CNT  22048    // counters
#define SMEM_FLOATS 22080
#define SMEM_BYTES (SMEM_FLOATS * 4)

// packed fp32x2 FMA (Blackwell)
#define FMA2(d, a, b) asm("fma.rn.f32x2 %0, %1, %2, %0;" : "+l"(d) : "l"(a), "l"(b))

static __device__ __forceinline__ unsigned long long pack2(float x) {
    unsigned long long r;
    unsigned int u = __float_as_uint(x);
    asm("mov.b64 %0, {%1, %1};" : "=l"(r) : "r"(u));
    return r;
}

// ---------------------------------------------------------------------------
// Kernel 1: S = src_features @ W1[:64,:] + b1 ; pack src positions
// ---------------------------------------------------------------------------
__global__ void __launch_bounds__(128) k_pre(
    const float* __restrict__ srcf, const float* __restrict__ srcp,
    const int* __restrict__ srcb, const float* __restrict__ W1,
    const float* __restrict__ b1)
{
    int j = blockIdx.x;
    int t = threadIdx.x;
    __shared__ float sx[DD];
    if (t < DD) sx[t] = srcf[j * DD + t];
    __syncthreads();
    float acc = b1[t];
#pragma unroll
    for (int d = 0; d < DD; d++) acc = fmaf(sx[d], W1[d * HH + t], acc);
    g_S[j * HH + t] = acc;
    if (t == 0) {
        g_spos[j] = make_float4(srcp[j * 3 + 0], srcp[j * 3 + 1],
                                srcp[j * 3 + 2], (float)srcb[j]);
    }
}

// ---------------------------------------------------------------------------
// Kernel 2: per-target fused ball-query + MLP + max aggregation
// ---------------------------------------------------------------------------
__global__ void __launch_bounds__(128) k_main(
    const float* __restrict__ tpos, const int* __restrict__ tbat,
    const float* __restrict__ W1, const float* __restrict__ W2g,
    const float* __restrict__ b2, float* __restrict__ out)
{
    extern __shared__ float sm[];
    float* sW2  = sm + OFF_W2;
    float* sH1  = sm + OFF_H1;
    float* sRed = sm + OFF_RED;
    float* cd2  = sm + OFF_CD2;
    float* srel = sm + OFF_CD2;                 // reused after selection
    int*   cidx = (int*)(sm + OFF_CIDX);
    int*   ssel = (int*)(sm + OFF_SEL);
    int*   scnt = (int*)(sm + OFF_CNT);

    const int t   = blockIdx.x;
    const int tid = threadIdx.x;

    if (tid == 0) scnt[0] = 0;

    // stage W2 into shared (read once per block, reused across 32 neighbors)
    {
        const float4* w4 = (const float4*)W2g;
        float4* s4 = (float4*)sW2;
#pragma unroll
        for (int i = 0; i < 32; i++) s4[tid + i * 128] = w4[tid + i * 128];
    }

    const float tx = tpos[t * 3 + 0];
    const float ty = tpos[t * 3 + 1];
    const float tz = tpos[t * 3 + 2];
    const float tbf = (float)tbat[t];
    const float R2 = (float)(0.12 * 0.12);   // match JAX rounding of python R*R

    __syncthreads();

    // ---- phase A: ball query (candidate collection) ----
    for (int s = tid; s < N_SRC; s += 128) {
        float4 p = g_spos[s];
        float dx = p.x - tx, dy = p.y - ty, dz = p.z - tz;
        float d2 = dx * dx + dy * dy + dz * dz;
        if (d2 <= R2 && p.w == tbf) {
            int c = atomicAdd(scnt, 1);
            if (c < CMAX) { cd2[c] = d2; cidx[c] = s; }
        }
    }
    __syncthreads();

    int C = min(scnt[0], CMAX);
    int selCnt = min(C, KN);

    // ---- phase B: exact nearest-K selection by rank (total order via idx tiebreak) ----
    if (C <= KN) {
        if (tid < C) ssel[tid] = cidx[tid];
    } else {
        for (int i = tid; i < C; i += 128) {
            float di = cd2[i];
            int   ii = cidx[i];
            int r = 0;
            for (int k2 = 0; k2 < C; k2++) {
                float dk = cd2[k2];
                r += (int)((dk < di) || (dk == di && cidx[k2] < ii));
            }
            if (r < KN) ssel[r] = cidx[i];   // ranks are unique -> no atomic
        }
    }
    __syncthreads();

    if (selCnt == 0) {                        // no neighbors -> zeros
        out[t * HH + tid] = 0.0f;
        return;
    }

    // stage relative positions (selection done; cd2 region is free)
    if (tid < selCnt) {
        float4 p = g_spos[ssel[tid]];
        srel[tid * 3 + 0] = p.x - tx;
        srel[tid * 3 + 1] = p.y - ty;
        srel[tid * 3 + 2] = p.z - tz;
    }
    __syncthreads();

    // ---- phase C: h1[n][c] = relu(S[j][c] + rel . W1p[:,c])  (b1 folded in S) ----
    {
        const float w0 = W1[64 * HH + tid];
        const float w1 = W1[65 * HH + tid];
        const float w2 = W1[66 * HH + tid];
        for (int n = 0; n < selCnt; n++) {
            int j = ssel[n];
            float v = g_S[j * HH + tid]
                    + srel[n * 3 + 0] * w0
                    + srel[n * 3 + 1] * w1
                    + srel[n * 3 + 2] * w2;
            sH1[n * HH + tid] = fmaxf(v, 0.0f);
        }
    }
    __syncthreads();

    // ---- phase D: C[32,128] = h1 @ W2, register-tiled, f32x2 packed FMA ----
    const int n_grp = tid & 15;
    const int m_grp = tid >> 4;
    const int m0 = m_grp * 4;
    const int cAi = n_grp * 4;        // channels cAi..cAi+3
    const int cBi = 64 + n_grp * 4;   // channels cBi..cBi+3

    unsigned long long acc[4][4];
#pragma unroll
    for (int i = 0; i < 4; i++)
#pragma unroll
        for (int j = 0; j < 4; j++) acc[i][j] = 0ull;

    for (int k = 0; k < HH; k += 4) {
        float4 a0 = *(const float4*)(sH1 + (m0 + 0) * HH + k);
        float4 a1 = *(const float4*)(sH1 + (m0 + 1) * HH + k);
        float4 a2 = *(const float4*)(sH1 + (m0 + 2) * HH + k);
        float4 a3 = *(const float4*)(sH1 + (m0 + 3) * HH + k);
        float am[4][4] = {{a0.x, a0.y, a0.z, a0.w},
                          {a1.x, a1.y, a1.z, a1.w},
                          {a2.x, a2.y, a2.z, a2.w},
                          {a3.x, a3.y, a3.z, a3.w}};
#pragma unroll
        for (int kk = 0; kk < 4; kk++) {
            const float* wrow = sW2 + (k + kk) * HH;
            ulonglong2 bA = *(const ulonglong2*)(wrow + cAi);
            ulonglong2 bB = *(const ulonglong2*)(wrow + cBi);
#pragma unroll
            for (int i = 0; i < 4; i++) {
                unsigned long long ap = pack2(am[i][kk]);
                FMA2(acc[i][0], ap, bA.x);
                FMA2(acc[i][1], ap, bA.y);
                FMA2(acc[i][2], ap, bB.x);
                FMA2(acc[i][3], ap, bB.y);
            }
        }
    }

    // ---- epilogue: +b2, relu, masked max over valid neighbor rows ----
    float4 b2A = *(const float4*)(b2 + cAi);
    float4 b2B = *(const float4*)(b2 + cBi);
    float bv[8] = {b2A.x, b2A.y, b2A.z, b2A.w, b2B.x, b2B.y, b2B.z, b2B.w};

    float pm[8];
#pragma unroll
    for (int j = 0; j < 8; j++) pm[j] = 0.0f;   // 0-init == mask + empty case (post-relu >= 0)

#pragma unroll
    for (int i = 0; i < 4; i++) {
        if (m0 + i < selCnt) {
#pragma unroll
            for (int j2 = 0; j2 < 4; j2++) {
                float lo = __uint_as_float((unsigned)(acc[i][j2] & 0xffffffffull));
                float hi = __uint_as_float((unsigned)(acc[i][j2] >> 32));
                pm[j2 * 2 + 0] = fmaxf(pm[j2 * 2 + 0], fmaxf(lo + bv[j2 * 2 + 0], 0.0f));
                pm[j2 * 2 + 1] = fmaxf(pm[j2 * 2 + 1], fmaxf(hi + bv[j2 * 2 + 1], 0.0f));
            }
        }
    }

#pragma unroll
    for (int q = 0; q < 4; q++) {
        sRed[m_grp * HH + cAi + q] = pm[q];
        sRed[m_grp * HH + cBi + q] = pm[4 + q];
    }
    __syncthreads();

    float r = 0.0f;
#pragma unroll
    for (int g = 0; g < 8; g++) r = fmaxf(r, sRed[g * HH + tid]);
    out[t * HH + tid] = r;
}

// ---------------------------------------------------------------------------
// Kernel 3: tuple tail (tgt_pos, tgt_batch) if the output buffer includes them
// ---------------------------------------------------------------------------
__global__ void k_tail(const float* __restrict__ tpos, const int* __restrict__ tb,
                       float* __restrict__ out, int mode)
{
    int i = blockIdx.x * blockDim.x + threadIdx.x;
    const int off = N_TGT * HH;
    if (i < N_TGT * 3) out[off + i] = tpos[i];
    if (mode >= 2 && i < N_TGT) out[off + N_TGT * 3 + i] = (float)tb[i];
}

// ---------------------------------------------------------------------------
extern "C" void kernel_launch(void* const* d_in, const int* in_sizes, int n_in,
                              void* d_out, int out_size)
{
    const float* srcf = (const float*)d_in[0];
    const float* srcp = (const float*)d_in[1];
    const int*   srcb = (const int*)d_in[2];
    // d_in[3] = tgt_features (unused by the reference)
    const float* tpos = (const float*)d_in[4];
    const int*   tbat = (const int*)d_in[5];
    const float* W1   = (const float*)d_in[6];
    const float* b1   = (const float*)d_in[7];
    const float* W2   = (const float*)d_in[8];
    const float* b2   = (const float*)d_in[9];
    float* out = (float*)d_out;

    cudaFuncSetAttribute(k_main, cudaFuncAttributeMaxDynamicSharedMemorySize, SMEM_BYTES);

    k_pre<<<N_SRC, 128>>>(srcf, srcp, srcb, W1, b1);
    k_main<<<N_TGT, 128, SMEM_BYTES>>>(tpos, tbat, W1, W2, b2, out);

    const int base = N_TGT * HH;
    if (out_size >= base + N_TGT * 3) {
        int mode = (out_size >= base + N_TGT * 3 + N_TGT) ? 2 : 1;
        int tot = N_TGT * 3;
        k_tail<<<(tot + 255) / 256, 256>>>(tpos, tbat, out, mode);
    }
}

// round 2
// speedup vs baseline: 1.0041x; 1.0041x over previous
#include <cuda_runtime.h>

#define N_SRC 8192
#define N_TGT 16384
#define DD 64
#define HH 128
#define KN 32
#define CMAX 256
#define NBLK 296          // 2 persistent blocks per SM (148 SMs)

// ---- device scratch (no allocations allowed) ----
static __device__ float  g_S[N_SRC * HH];     // src_features @ W1[:64] + b1
static __device__ float4 g_spos[N_SRC];       // packed src pos + (float)batch
static __device__ float  g_ss[N_SRC];         // |src_pos|^2 (gram-trick term)

// ---- shared memory layout for k_main (offsets in floats) ----
#define OFF_W2   0        // 16384  (128x128 W2)
#define OFF_H1   16384    // 4096   (h1[32][128])
#define OFF_RED  20480    // 1024   (8 m-groups x 128 channels)
#define OFF_CD2  21504    // 256    (candidate d2; reused as rel[32][3])
#define OFF_CIDX 21760    // 256    (candidate idx, int)
#define OFF_SEL  22016    // 32     (selected idx, int)
#define OFF_CNT  22048    // counter
#define SMEM_FLOATS 22080
#define SMEM_BYTES (SMEM_FLOATS * 4)

// packed fp32x2 FMA (Blackwell)
#define FMA2(d, a, b) asm("fma.rn.f32x2 %0, %1, %2, %0;" : "+l"(d) : "l"(a), "l"(b))

static __device__ __forceinline__ unsigned long long pack2(float x) {
    unsigned long long r;
    unsigned int u = __float_as_uint(x);
    asm("mov.b64 %0, {%1, %1};" : "=l"(r) : "r"(u));
    return r;
}

// ---------------------------------------------------------------------------
// Kernel 1: S = src_features @ W1[:64,:] + b1 ; pack src positions; |pos|^2
// ---------------------------------------------------------------------------
__global__ void __launch_bounds__(128) k_pre(
    const float* __restrict__ srcf, const float* __restrict__ srcp,
    const int* __restrict__ srcb, const float* __restrict__ W1,
    const float* __restrict__ b1)
{
    int j = blockIdx.x;
    int t = threadIdx.x;
    __shared__ float sx[DD];
    if (t < DD) sx[t] = srcf[j * DD + t];
    __syncthreads();
    float acc = b1[t];
#pragma unroll
    for (int d = 0; d < DD; d++) acc = fmaf(sx[d], W1[d * HH + t], acc);
    g_S[j * HH + t] = acc;
    if (t == 0) {
        float x = srcp[j * 3 + 0], y = srcp[j * 3 + 1], z = srcp[j * 3 + 2];
        g_spos[j] = make_float4(x, y, z, (float)srcb[j]);
        g_ss[j] = x * x + y * y + z * z;   // match jnp.sum(p*p) order
    }
}

// ---------------------------------------------------------------------------
// Kernel 2: persistent blocks; per-target fused ball-query + MLP + max agg
// ---------------------------------------------------------------------------
__global__ void __launch_bounds__(128) k_main(
    const float* __restrict__ tpos, const int* __restrict__ tbat,
    const float* __restrict__ W1, const float* __restrict__ W2g,
    const float* __restrict__ b2, float* __restrict__ out)
{
    extern __shared__ float sm[];
    float* sW2  = sm + OFF_W2;
    float* sH1  = sm + OFF_H1;
    float* sRed = sm + OFF_RED;
    float* cd2  = sm + OFF_CD2;
    float* srel = sm + OFF_CD2;                 // reused after selection
    int*   cidx = (int*)(sm + OFF_CIDX);
    int*   ssel = (int*)(sm + OFF_SEL);
    int*   scnt = (int*)(sm + OFF_CNT);

    const int tid = threadIdx.x;

    // ---- stage W2 once per persistent block ----
    {
        const float4* w4 = (const float4*)W2g;
        float4* s4 = (float4*)sW2;
#pragma unroll
        for (int i = 0; i < 32; i++) s4[tid + i * 128] = w4[tid + i * 128];
    }

    // per-thread constants
    const float w10 = W1[64 * HH + tid];
    const float w11 = W1[65 * HH + tid];
    const float w12 = W1[66 * HH + tid];
    const float R2  = (float)(0.12 * 0.12);

    const int n_grp = tid & 15;
    const int m_grp = tid >> 4;
    const int m0  = m_grp * 4;
    const int cAi = n_grp * 4;
    const int cBi = 64 + n_grp * 4;
    const float4 b2A = *(const float4*)(b2 + cAi);
    const float4 b2B = *(const float4*)(b2 + cBi);
    const float bv[8] = {b2A.x, b2A.y, b2A.z, b2A.w, b2B.x, b2B.y, b2B.z, b2B.w};

    __syncthreads();

    for (int t = blockIdx.x; t < N_TGT; t += NBLK) {
        const float tx = tpos[t * 3 + 0];
        const float ty = tpos[t * 3 + 1];
        const float tz = tpos[t * 3 + 2];
        const float tbf = (float)tbat[t];
        const float tt = tx * tx + ty * ty + tz * tz;   // match jnp.sum order

        if (tid == 0) scnt[0] = 0;
        __syncthreads();   // scnt visible; prior-iteration smem reads complete

        // ---- phase A: ball query, gram-trick d2 to match reference ----
        for (int s = tid; s < N_SRC; s += 128) {
            float4 p = g_spos[s];
            float dot = tx * p.x + ty * p.y + tz * p.z;
            float d2 = (tt + g_ss[s]) - 2.0f * dot;
            if (d2 <= R2 && p.w == tbf) {
                int c = atomicAdd(scnt, 1);
                if (c < CMAX) { cd2[c] = d2; cidx[c] = s; }
            }
        }
        __syncthreads();

        const int C = min(scnt[0], CMAX);
        const int selCnt = min(C, KN);

        // ---- phase B: exact nearest-K by rank (stable: idx tiebreak) ----
        if (C <= KN) {
            if (tid < C) ssel[tid] = cidx[tid];
        } else {
            for (int i = tid; i < C; i += 128) {
                float di = cd2[i];
                int   ii = cidx[i];
                int r = 0;
                for (int k2 = 0; k2 < C; k2++) {
                    float dk = cd2[k2];
                    r += (int)((dk < di) || (dk == di && cidx[k2] < ii));
                }
                if (r < KN) ssel[r] = cidx[i];
            }
        }
        __syncthreads();

        if (selCnt == 0) {                    // uniform branch (selCnt same all threads)
            out[t * HH + tid] = 0.0f;
            __syncthreads();                  // keep barrier schedule uniform w.r.t. smem reuse
            continue;
        }

        // stage relative positions (cd2 region free after selection)
        if (tid < selCnt) {
            float4 p = g_spos[ssel[tid]];
            srel[tid * 3 + 0] = p.x - tx;
            srel[tid * 3 + 1] = p.y - ty;
            srel[tid * 3 + 2] = p.z - tz;
        }
        __syncthreads();

        // ---- phase C: h1[n][c] = relu(S[j][c] + rel.W1p[:,c]) ----
        // fixed trip count + clamp -> full unroll -> deep LDG pipeline
#pragma unroll
        for (int n = 0; n < KN; n++) {
            int nn = (n < selCnt) ? n : 0;
            int j = ssel[nn];
            float v = g_S[j * HH + tid]
                    + srel[nn * 3 + 0] * w10
                    + srel[nn * 3 + 1] * w11
                    + srel[nn * 3 + 2] * w12;
            sH1[n * HH + tid] = fmaxf(v, 0.0f);   // rows >= selCnt hold dupes; masked later
        }
        __syncthreads();

        // ---- phase D: C[32,128] = h1 @ W2, 4m x 8n per thread, f32x2 FMA ----
        unsigned long long acc[4][4];
#pragma unroll
        for (int i = 0; i < 4; i++)
#pragma unroll
            for (int j = 0; j < 4; j++) acc[i][j] = 0ull;

        for (int k = 0; k < HH; k += 4) {
            float4 a0 = *(const float4*)(sH1 + (m0 + 0) * HH + k);
            float4 a1 = *(const float4*)(sH1 + (m0 + 1) * HH + k);
            float4 a2 = *(const float4*)(sH1 + (m0 + 2) * HH + k);
            float4 a3 = *(const float4*)(sH1 + (m0 + 3) * HH + k);
            float am[4][4] = {{a0.x, a0.y, a0.z, a0.w},
                              {a1.x, a1.y, a1.z, a1.w},
                              {a2.x, a2.y, a2.z, a2.w},
                              {a3.x, a3.y, a3.z, a3.w}};
#pragma unroll
            for (int kk = 0; kk < 4; kk++) {
                const float* wrow = sW2 + (k + kk) * HH;
                ulonglong2 bA = *(const ulonglong2*)(wrow + cAi);
                ulonglong2 bB = *(const ulonglong2*)(wrow + cBi);
#pragma unroll
                for (int i = 0; i < 4; i++) {
                    unsigned long long ap = pack2(am[i][kk]);
                    FMA2(acc[i][0], ap, bA.x);
                    FMA2(acc[i][1], ap, bA.y);
                    FMA2(acc[i][2], ap, bB.x);
                    FMA2(acc[i][3], ap, bB.y);
                }
            }
        }

        // ---- epilogue: +b2, relu, masked max over valid rows ----
        float pm[8];
#pragma unroll
        for (int j = 0; j < 8; j++) pm[j] = 0.0f;   // 0-init == mask + empty case

#pragma unroll
        for (int i = 0; i < 4; i++) {
            if (m0 + i < selCnt) {
#pragma unroll
                for (int j2 = 0; j2 < 4; j2++) {
                    float lo = __uint_as_float((unsigned)(acc[i][j2] & 0xffffffffull));
                    float hi = __uint_as_float((unsigned)(acc[i][j2] >> 32));
                    pm[j2 * 2 + 0] = fmaxf(pm[j2 * 2 + 0], fmaxf(lo + bv[j2 * 2 + 0], 0.0f));
                    pm[j2 * 2 + 1] = fmaxf(pm[j2 * 2 + 1], fmaxf(hi + bv[j2 * 2 + 1], 0.0f));
                }
            }
        }

#pragma unroll
        for (int q = 0; q < 4; q++) {
            sRed[m_grp * HH + cAi + q] = pm[q];
            sRed[m_grp * HH + cBi + q] = pm[4 + q];
        }
        __syncthreads();

        float r = 0.0f;
#pragma unroll
        for (int g = 0; g < 8; g++) r = fmaxf(r, sRed[g * HH + tid]);
        out[t * HH + tid] = r;
        __syncthreads();   // sRed reads complete before next iteration reuses smem
    }
}

// ---------------------------------------------------------------------------
// Kernel 3: tuple tail (tgt_pos, tgt_batch) if the output buffer includes them
// ---------------------------------------------------------------------------
__global__ void k_tail(const float* __restrict__ tpos, const int* __restrict__ tb,
                       float* __restrict__ out, int mode)
{
    int i = blockIdx.x * blockDim.x + threadIdx.x;
    const int off = N_TGT * HH;
    if (i < N_TGT * 3) out[off + i] = tpos[i];
    if (mode >= 2 && i < N_TGT) out[off + N_TGT * 3 + i] = (float)tb[i];
}

// ---------------------------------------------------------------------------
extern "C" void kernel_launch(void* const* d_in, const int* in_sizes, int n_in,
                              void* d_out, int out_size)
{
    const float* srcf = (const float*)d_in[0];
    const float* srcp = (const float*)d_in[1];
    const int*   srcb = (const int*)d_in[2];
    // d_in[3] = tgt_features (unused by the reference)
    const float* tpos = (const float*)d_in[4];
    const int*   tbat = (const int*)d_in[5];
    const float* W1   = (const float*)d_in[6];
    const float* b1   = (const float*)d_in[7];
    const float* W2   = (const float*)d_in[8];
    const float* b2   = (const float*)d_in[9];
    float* out = (float*)d_out;

    cudaFuncSetAttribute(k_main, cudaFuncAttributeMaxDynamicSharedMemorySize, SMEM_BYTES);

    k_pre<<<N_SRC, 128>>>(srcf, srcp, srcb, W1, b1);
    k_main<<<NBLK, 128, SMEM_BYTES>>>(tpos, tbat, W1, W2, b2, out);

    const int base = N_TGT * HH;
    if (out_size >= base + N_TGT * 3) {
        int mode = (out_size >= base + N_TGT * 3 + N_TGT) ? 2 : 1;
        int tot = N_TGT * 3;
        k_tail<<<(tot + 255) / 256, 256>>>(tpos, tbat, out, mode);
    }
}

// round 3
// speedup vs baseline: 1.1600x; 1.1552x over previous
#include <cuda_runtime.h>

#define N_SRC 8192
#define N_TGT 16384
#define DD 64
#define HH 128
#define KN 32
#define CMAX 256
#define NBLK 296          // 2 persistent blocks per SM
#define GRID 8            // 8x8x8 spatial bins, cell = 0.125
#define NCELL (GRID*GRID*GRID)

// ---- device scratch (no allocations allowed) ----
static __device__ float  g_S[N_SRC * HH];     // src_features @ W1[:64] + b1
static __device__ float4 g_spos[N_SRC];       // orig-indexed pos (+batch)
static __device__ float  g_ss[N_SRC];         // |src_pos|^2
static __device__ int    g_cell[N_SRC];
static __device__ int    g_cnt[NCELL];
static __device__ int    g_fill[NCELL];
static __device__ int    g_start[NCELL + 1];
static __device__ float4 g_bp[N_SRC];         // binned: (x, y, z, ss)
static __device__ int    g_bidx[N_SRC];       // binned -> orig idx

// ---- shared memory layout for k_main (offsets in floats) ----
#define OFF_W2   0        // 16384
#define OFF_H1   16384    // 4096
#define OFF_RED  20480    // 1024
#define OFF_CD2  21504    // 256 (candidate d2; reused as rel[32][3])
#define OFF_CIDX 21760    // 256
#define OFF_SEL  22016    // 32
#define OFF_CNT  22048    // 1 counter
#define OFF_SPAN 22056    // 9 span starts + 10 cum + 1 nspan = 20 ints
#define SMEM_FLOATS 22080
#define SMEM_BYTES (SMEM_FLOATS * 4)

#define FMA2(d, a, b) asm("fma.rn.f32x2 %0, %1, %2, %0;" : "+l"(d) : "l"(a), "l"(b))

static __device__ __forceinline__ unsigned long long pack2(float x) {
    unsigned long long r;
    unsigned int u = __float_as_uint(x);
    asm("mov.b64 %0, {%1, %1};" : "=l"(r) : "r"(u));
    return r;
}

static __device__ __forceinline__ int cell_of(float x, float y, float z) {
    int cx = min(GRID - 1, max(0, (int)floorf(x * (float)GRID)));
    int cy = min(GRID - 1, max(0, (int)floorf(y * (float)GRID)));
    int cz = min(GRID - 1, max(0, (int)floorf(z * (float)GRID)));
    return (cz * GRID + cy) * GRID + cx;
}

// ---------------------------------------------------------------------------
__global__ void k_zero() {
    int i = blockIdx.x * blockDim.x + threadIdx.x;
    if (i < NCELL) { g_cnt[i] = 0; g_fill[i] = 0; }
}

// Kernel: S = src_features @ W1[:64,:] + b1 ; pos pack; ss; cell counts
__global__ void __launch_bounds__(128) k_pre(
    const float* __restrict__ srcf, const float* __restrict__ srcp,
    const int* __restrict__ srcb, const float* __restrict__ W1,
    const float* __restrict__ b1)
{
    const int j0 = blockIdx.x * 4;
    const int t = threadIdx.x;
    __shared__ float sx[4][DD];
    for (int i = t; i < 4 * DD; i += 128) sx[i / DD][i % DD] = srcf[j0 * DD + i];
    __syncthreads();
    float a0, a1, a2, a3;
    a0 = a1 = a2 = a3 = b1[t];
#pragma unroll
    for (int d = 0; d < DD; d++) {
        float w = W1[d * HH + t];
        a0 = fmaf(sx[0][d], w, a0);
        a1 = fmaf(sx[1][d], w, a1);
        a2 = fmaf(sx[2][d], w, a2);
        a3 = fmaf(sx[3][d], w, a3);
    }
    g_S[(j0 + 0) * HH + t] = a0;
    g_S[(j0 + 1) * HH + t] = a1;
    g_S[(j0 + 2) * HH + t] = a2;
    g_S[(j0 + 3) * HH + t] = a3;
    if (t < 4) {
        int j = j0 + t;
        float x = srcp[j * 3 + 0], y = srcp[j * 3 + 1], z = srcp[j * 3 + 2];
        g_spos[j] = make_float4(x, y, z, (float)srcb[j]);
        g_ss[j] = x * x + y * y + z * z;
        int c = cell_of(x, y, z);
        g_cell[j] = c;
        atomicAdd(&g_cnt[c], 1);
    }
}

// exclusive prefix over 512 cell counts (single block)
__global__ void __launch_bounds__(NCELL) k_scan() {
    __shared__ int s[NCELL];
    int t = threadIdx.x;
    s[t] = g_cnt[t];
    __syncthreads();
#pragma unroll
    for (int off = 1; off < NCELL; off <<= 1) {
        int v = (t >= off) ? s[t - off] : 0;
        __syncthreads();
        s[t] += v;
        __syncthreads();
    }
    g_start[t + 1] = s[t];          // inclusive at t -> exclusive start at t+1
    if (t == 0) g_start[0] = 0;
}

__global__ void __launch_bounds__(128) k_scatter() {
    int j = blockIdx.x * 128 + threadIdx.x;
    if (j >= N_SRC) return;
    int c = g_cell[j];
    int off = atomicAdd(&g_fill[c], 1);
    int dst = g_start[c] + off;
    float4 p = g_spos[j];
    g_bp[dst] = make_float4(p.x, p.y, p.z, g_ss[j]);
    g_bidx[dst] = j;
}

// ---------------------------------------------------------------------------
// main: persistent blocks; binned ball-query + fused MLP + max aggregation
// ---------------------------------------------------------------------------
__global__ void __launch_bounds__(128) k_main(
    const float* __restrict__ tpos, const int* __restrict__ tbat,
    const float* __restrict__ W1, const float* __restrict__ W2g,
    const float* __restrict__ b2, float* __restrict__ out)
{
    extern __shared__ float sm[];
    float* sW2  = sm + OFF_W2;
    float* sH1  = sm + OFF_H1;
    float* sRed = sm + OFF_RED;
    float* cd2  = sm + OFF_CD2;
    float* srel = sm + OFF_CD2;
    int*   cidx = (int*)(sm + OFF_CIDX);
    int*   ssel = (int*)(sm + OFF_SEL);
    int*   scnt = (int*)(sm + OFF_CNT);
    int*   span_s = (int*)(sm + OFF_SPAN);       // [9]
    int*   span_c = (int*)(sm + OFF_SPAN) + 9;   // [10] cumulative
    int*   span_n = (int*)(sm + OFF_SPAN) + 19;  // nspan

    const int tid = threadIdx.x;

    { // stage W2 once per persistent block
        const float4* w4 = (const float4*)W2g;
        float4* s4 = (float4*)sW2;
#pragma unroll
        for (int i = 0; i < 32; i++) s4[tid + i * 128] = w4[tid + i * 128];
    }

    const float w10 = W1[64 * HH + tid];
    const float w11 = W1[65 * HH + tid];
    const float w12 = W1[66 * HH + tid];
    const float R2  = (float)(0.12 * 0.12);

    const int n_grp = tid & 15;
    const int m_grp = tid >> 4;
    const int m0  = m_grp * 4;
    const int cAi = n_grp * 4;
    const int cBi = 64 + n_grp * 4;
    const float4 b2A = *(const float4*)(b2 + cAi);
    const float4 b2B = *(const float4*)(b2 + cBi);
    const float bv[8] = {b2A.x, b2A.y, b2A.z, b2A.w, b2B.x, b2B.y, b2B.z, b2B.w};

    __syncthreads();

    for (int t = blockIdx.x; t < N_TGT; t += NBLK) {
        const float tx = tpos[t * 3 + 0];
        const float ty = tpos[t * 3 + 1];
        const float tz = tpos[t * 3 + 2];
        const float tt = tx * tx + ty * ty + tz * tz;

        if (tid == 0) {
            scnt[0] = 0;
            // build candidate spans from the bin grid (<=27 cells, <=9 x-spans)
            const float RM = 0.121f;   // radius + slack for fp rounding
            int lx = max(0, (int)floorf((tx - RM) * (float)GRID));
            int hx = min(GRID - 1, (int)floorf((tx + RM) * (float)GRID));
            int ly = max(0, (int)floorf((ty - RM) * (float)GRID));
            int hy = min(GRID - 1, (int)floorf((ty + RM) * (float)GRID));
            int lz = max(0, (int)floorf((tz - RM) * (float)GRID));
            int hz = min(GRID - 1, (int)floorf((tz + RM) * (float)GRID));
            int ns = 0, tot = 0;
            span_c[0] = 0;
            for (int cz = lz; cz <= hz; cz++)
                for (int cy = ly; cy <= hy; cy++) {
                    int cbase = (cz * GRID + cy) * GRID;
                    int s0 = g_start[cbase + lx];
                    int s1 = g_start[cbase + hx + 1];
                    span_s[ns] = s0;
                    tot += s1 - s0;
                    span_c[ns + 1] = tot;
                    ns++;
                }
            span_n[0] = ns;
        }
        __syncthreads();

        // ---- phase A: scan flattened candidate spans ----
        {
            const int ns = span_n[0];
            const int T = span_c[ns];
            for (int i = tid; i < T; i += 128) {
                int sp = 0;
                while (i >= span_c[sp + 1]) sp++;
                int s = span_s[sp] + (i - span_c[sp]);
                float4 p = g_bp[s];               // w = ss
                float dot = tx * p.x + ty * p.y + tz * p.z;
                float d2 = (tt + p.w) - 2.0f * dot;
                if (d2 <= R2) {
                    int c = atomicAdd(scnt, 1);
                    if (c < CMAX) { cd2[c] = d2; cidx[c] = g_bidx[s]; }
                }
            }
        }
        __syncthreads();

        const int C = min(scnt[0], CMAX);
        const int selCnt = min(C, KN);

        // ---- phase B: exact nearest-K by rank (ties: smaller orig idx) ----
        if (C <= KN) {
            if (tid < C) ssel[tid] = cidx[tid];
        } else {
            for (int i = tid; i < C; i += 128) {
                float di = cd2[i];
                int   ii = cidx[i];
                int r = 0;
                for (int k2 = 0; k2 < C; k2++) {
                    float dk = cd2[k2];
                    r += (int)((dk < di) || (dk == di && cidx[k2] < ii));
                }
                if (r < KN) ssel[r] = cidx[i];
            }
        }
        __syncthreads();

        if (selCnt == 0) {
            out[t * HH + tid] = 0.0f;
            __syncthreads();
            continue;
        }

        if (tid < selCnt) {
            float4 p = g_spos[ssel[tid]];
            srel[tid * 3 + 0] = p.x - tx;
            srel[tid * 3 + 1] = p.y - ty;
            srel[tid * 3 + 2] = p.z - tz;
        }
        __syncthreads();

        // ---- phase C: h1[n][c] = relu(S[j][c] + rel . W1p[:,c]) ----
#pragma unroll
        for (int n = 0; n < KN; n++) {
            int nn = (n < selCnt) ? n : 0;
            int j = ssel[nn];
            float v = g_S[j * HH + tid]
                    + srel[nn * 3 + 0] * w10
                    + srel[nn * 3 + 1] * w11
                    + srel[nn * 3 + 2] * w12;
            sH1[n * HH + tid] = fmaxf(v, 0.0f);
        }
        __syncthreads();

        // ---- phase D: [32,128] = h1 @ W2, 4m x 8n per thread, f32x2 FMA ----
        unsigned long long acc[4][4];
#pragma unroll
        for (int i = 0; i < 4; i++)
#pragma unroll
            for (int j = 0; j < 4; j++) acc[i][j] = 0ull;

        for (int k = 0; k < HH; k += 4) {
            float4 a0 = *(const float4*)(sH1 + (m0 + 0) * HH + k);
            float4 a1 = *(const float4*)(sH1 + (m0 + 1) * HH + k);
            float4 a2 = *(const float4*)(sH1 + (m0 + 2) * HH + k);
            float4 a3 = *(const float4*)(sH1 + (m0 + 3) * HH + k);
            float am[4][4] = {{a0.x, a0.y, a0.z, a0.w},
                              {a1.x, a1.y, a1.z, a1.w},
                              {a2.x, a2.y, a2.z, a2.w},
                              {a3.x, a3.y, a3.z, a3.w}};
#pragma unroll
            for (int kk = 0; kk < 4; kk++) {
                const float* wrow = sW2 + (k + kk) * HH;
                ulonglong2 bA = *(const ulonglong2*)(wrow + cAi);
                ulonglong2 bB = *(const ulonglong2*)(wrow + cBi);
#pragma unroll
                for (int i = 0; i < 4; i++) {
                    unsigned long long ap = pack2(am[i][kk]);
                    FMA2(acc[i][0], ap, bA.x);
                    FMA2(acc[i][1], ap, bA.y);
                    FMA2(acc[i][2], ap, bB.x);
                    FMA2(acc[i][3], ap, bB.y);
                }
            }
        }

        // ---- epilogue: +b2, relu, masked max ----
        float pm[8];
#pragma unroll
        for (int j = 0; j < 8; j++) pm[j] = 0.0f;

#pragma unroll
        for (int i = 0; i < 4; i++) {
            if (m0 + i < selCnt) {
#pragma unroll
                for (int j2 = 0; j2 < 4; j2++) {
                    float lo = __uint_as_float((unsigned)(acc[i][j2] & 0xffffffffull));
                    float hi = __uint_as_float((unsigned)(acc[i][j2] >> 32));
                    pm[j2 * 2 + 0] = fmaxf(pm[j2 * 2 + 0], fmaxf(lo + bv[j2 * 2 + 0], 0.0f));
                    pm[j2 * 2 + 1] = fmaxf(pm[j2 * 2 + 1], fmaxf(hi + bv[j2 * 2 + 1], 0.0f));
                }
            }
        }

#pragma unroll
        for (int q = 0; q < 4; q++) {
            sRed[m_grp * HH + cAi + q] = pm[q];
            sRed[m_grp * HH + cBi + q] = pm[4 + q];
        }
        __syncthreads();

        float r = 0.0f;
#pragma unroll
        for (int g = 0; g < 8; g++) r = fmaxf(r, sRed[g * HH + tid]);
        out[t * HH + tid] = r;
        __syncthreads();
    }
}

// ---------------------------------------------------------------------------
__global__ void k_tail(const float* __restrict__ tpos, const int* __restrict__ tb,
                       float* __restrict__ out, int mode)
{
    int i = blockIdx.x * blockDim.x + threadIdx.x;
    const int off = N_TGT * HH;
    if (i < N_TGT * 3) out[off + i] = tpos[i];
    if (mode >= 2 && i < N_TGT) out[off + N_TGT * 3 + i] = (float)tb[i];
}

// ---------------------------------------------------------------------------
extern "C" void kernel_launch(void* const* d_in, const int* in_sizes, int n_in,
                              void* d_out, int out_size)
{
    const float* srcf = (const float*)d_in[0];
    const float* srcp = (const float*)d_in[1];
    const int*   srcb = (const int*)d_in[2];
    const float* tpos = (const float*)d_in[4];
    const int*   tbat = (const int*)d_in[5];
    const float* W1   = (const float*)d_in[6];
    const float* b1   = (const float*)d_in[7];
    const float* W2   = (const float*)d_in[8];
    const float* b2   = (const float*)d_in[9];
    float* out = (float*)d_out;

    cudaFuncSetAttribute(k_main, cudaFuncAttributeMaxDynamicSharedMemorySize, SMEM_BYTES);

    k_zero<<<(NCELL + 255) / 256, 256>>>();
    k_pre<<<N_SRC / 4, 128>>>(srcf, srcp, srcb, W1, b1);
    k_scan<<<1, NCELL>>>();
    k_scatter<<<N_SRC / 128, 128>>>();
    k_main<<<NBLK, 128, SMEM_BYTES>>>(tpos, tbat, W1, W2, b2, out);

    const int base = N_TGT * HH;
    if (out_size >= base + N_TGT * 3) {
        int mode = (out_size >= base + N_TGT * 3 + N_TGT) ? 2 : 1;
        int tot = N_TGT * 3;
        k_tail<<<(tot + 255) / 256, 256>>>(tpos, tbat, out, mode);
    }
}

// round 6
// speedup vs baseline: 2.8364x; 2.4453x over previous
#include <cuda_runtime.h>
#include <cuda_bf16.h>
#include <mma.h>
#include <cstdint>

using namespace nvcuda;

#define N_SRC 8192
#define N_TGT 16384
#define DD 64
#define HH 128
#define KN 32
#define CMAX 256
#define GRID 8
#define NCELL (GRID*GRID*GRID)
#define NTILE (N_TGT / 4)          // 4096 tiles of 4 targets
#define NBLK_G 148                 // persistent GEMM blocks (1/SM)

#define LDA 136                    // bf16 leading dim (136*2 = 272B, 16B-mult)
#define LDC 132                    // fp32 leading dim (132*4 = 528B, 16B-mult)

// ---------------- device scratch ----------------
static __device__ float  g_S[N_SRC * HH];
static __device__ float4 g_spos[N_SRC];
static __device__ float  g_ss[N_SRC];
static __device__ int    g_cell[N_SRC];
static __device__ int    g_cnt[NCELL];
static __device__ int    g_fill[NCELL];
static __device__ int    g_start[NCELL + 1];
static __device__ float4 g_bp[N_SRC];
static __device__ int    g_bidx[N_SRC];
static __device__ float4 g_nbr[N_TGT * KN];   // (relx, rely, relz, bitcast j or -1)
static __device__ int    g_scnt[N_TGT];

// ---------------- k_gemm smem layout (bytes) ----------------
#define SM_BHI   0                       // 128*136*2 = 34816
#define SM_BLO   34816
#define SM_AHI   69632                   // reused as C (fp32 128x132 = 67584)
#define SM_ALO   104448
#define SM_C     69632
#define SM_W1    139264                  // 3*128*4 = 1536
#define SM_B2    140800                  // 512
#define SM_NBR   141312                  // 128*16 = 2048
#define SM_SC    143360                  // 4 ints
#define SMEM_G   143392

static __device__ __forceinline__ int cell_of(float x, float y, float z) {
    int cx = min(GRID - 1, max(0, (int)floorf(x * (float)GRID)));
    int cy = min(GRID - 1, max(0, (int)floorf(y * (float)GRID)));
    int cz = min(GRID - 1, max(0, (int)floorf(z * (float)GRID)));
    return (cz * GRID + cy) * GRID + cx;
}

// ---------------------------------------------------------------------------
__global__ void k_zero() {
    int i = blockIdx.x * blockDim.x + threadIdx.x;
    if (i < NCELL) { g_cnt[i] = 0; g_fill[i] = 0; }
}

__global__ void __launch_bounds__(128) k_pre(
    const float* __restrict__ srcf, const float* __restrict__ srcp,
    const int* __restrict__ srcb, const float* __restrict__ W1,
    const float* __restrict__ b1)
{
    const int j0 = blockIdx.x * 4;
    const int t = threadIdx.x;
    __shared__ float sx[4][DD];
    for (int i = t; i < 4 * DD; i += 128) sx[i / DD][i % DD] = srcf[j0 * DD + i];
    __syncthreads();
    float a0, a1, a2, a3;
    a0 = a1 = a2 = a3 = b1[t];
#pragma unroll
    for (int d = 0; d < DD; d++) {
        float w = W1[d * HH + t];
        a0 = fmaf(sx[0][d], w, a0);
        a1 = fmaf(sx[1][d], w, a1);
        a2 = fmaf(sx[2][d], w, a2);
        a3 = fmaf(sx[3][d], w, a3);
    }
    g_S[(j0 + 0) * HH + t] = a0;
    g_S[(j0 + 1) * HH + t] = a1;
    g_S[(j0 + 2) * HH + t] = a2;
    g_S[(j0 + 3) * HH + t] = a3;
    if (t < 4) {
        int j = j0 + t;
        float x = srcp[j * 3 + 0], y = srcp[j * 3 + 1], z = srcp[j * 3 + 2];
        g_spos[j] = make_float4(x, y, z, (float)srcb[j]);
        g_ss[j] = x * x + y * y + z * z;
        int c = cell_of(x, y, z);
        g_cell[j] = c;
        atomicAdd(&g_cnt[c], 1);
    }
}

__global__ void __launch_bounds__(NCELL) k_scan() {
    __shared__ int s[NCELL];
    int t = threadIdx.x;
    s[t] = g_cnt[t];
    __syncthreads();
#pragma unroll
    for (int off = 1; off < NCELL; off <<= 1) {
        int v = (t >= off) ? s[t - off] : 0;
        __syncthreads();
        s[t] += v;
        __syncthreads();
    }
    g_start[t + 1] = s[t];
    if (t == 0) g_start[0] = 0;
}

__global__ void __launch_bounds__(128) k_scatter() {
    int j = blockIdx.x * 128 + threadIdx.x;
    if (j >= N_SRC) return;
    int c = g_cell[j];
    int off = atomicAdd(&g_fill[c], 1);
    int dst = g_start[c] + off;
    float4 p = g_spos[j];
    g_bp[dst] = make_float4(p.x, p.y, p.z, g_ss[j]);
    g_bidx[dst] = j;
}

// ---------------------------------------------------------------------------
// search: one block per target -> neighbor list (rel, idx) + count
// ---------------------------------------------------------------------------
__global__ void __launch_bounds__(128) k_search(const float* __restrict__ tpos)
{
    __shared__ float cd2[CMAX];
    __shared__ int   cidx[CMAX];
    __shared__ int   ssel[KN];
    __shared__ int   scnt;
    __shared__ int   span_s[9], span_c[10], span_n;

    const int t = blockIdx.x;
    const int tid = threadIdx.x;

    const float tx = tpos[t * 3 + 0];
    const float ty = tpos[t * 3 + 1];
    const float tz = tpos[t * 3 + 2];
    const float tt = tx * tx + ty * ty + tz * tz;
    const float R2 = (float)(0.12 * 0.12);

    if (tid == 0) {
        scnt = 0;
        const float RM = 0.121f;
        int lx = max(0, (int)floorf((tx - RM) * (float)GRID));
        int hx = min(GRID - 1, (int)floorf((tx + RM) * (float)GRID));
        int ly = max(0, (int)floorf((ty - RM) * (float)GRID));
        int hy = min(GRID - 1, (int)floorf((ty + RM) * (float)GRID));
        int lz = max(0, (int)floorf((tz - RM) * (float)GRID));
        int hz = min(GRID - 1, (int)floorf((tz + RM) * (float)GRID));
        int ns = 0, tot = 0;
        span_c[0] = 0;
        for (int cz = lz; cz <= hz; cz++)
            for (int cy = ly; cy <= hy; cy++) {
                int cbase = (cz * GRID + cy) * GRID;
                int s0 = g_start[cbase + lx];
                int s1 = g_start[cbase + hx + 1];
                span_s[ns] = s0;
                tot += s1 - s0;
                span_c[ns + 1] = tot;
                ns++;
            }
        span_n = ns;
    }
    __syncthreads();

    {
        const int ns = span_n;
        const int T = span_c[ns];
        for (int i = tid; i < T; i += 128) {
            int sp = 0;
            while (i >= span_c[sp + 1]) sp++;
            int s = span_s[sp] + (i - span_c[sp]);
            float4 p = g_bp[s];
            float dot = tx * p.x + ty * p.y + tz * p.z;
            float d2 = (tt + p.w) - 2.0f * dot;
            if (d2 <= R2) {
                int c = atomicAdd(&scnt, 1);
                if (c < CMAX) { cd2[c] = d2; cidx[c] = g_bidx[s]; }
            }
        }
    }
    __syncthreads();

    const int C = min(scnt, CMAX);
    const int selCnt = min(C, KN);

    if (C <= KN) {
        if (tid < C) ssel[tid] = cidx[tid];
    } else {
        for (int i = tid; i < C; i += 128) {
            float di = cd2[i];
            int   ii = cidx[i];
            int r = 0;
            for (int k2 = 0; k2 < C; k2++) {
                float dk = cd2[k2];
                r += (int)((dk < di) || (dk == di && cidx[k2] < ii));
            }
            if (r < KN) ssel[r] = cidx[i];
        }
    }
    __syncthreads();

    if (tid < KN) {
        if (tid < selCnt) {
            int j = ssel[tid];
            float4 p = g_spos[j];
            g_nbr[t * KN + tid] = make_float4(p.x - tx, p.y - ty, p.z - tz,
                                              __int_as_float(j));
        } else {
            g_nbr[t * KN + tid] = make_float4(0.f, 0.f, 0.f, __int_as_float(-1));
        }
    }
    if (tid == 0) g_scnt[t] = selCnt;
}

// ---------------------------------------------------------------------------
// GEMM: persistent; per tile 4 targets x 32 nbrs; split-bf16 WMMA (HMMA)
// ---------------------------------------------------------------------------
__global__ void __launch_bounds__(256) k_gemm(
    const float* __restrict__ W1, const float* __restrict__ W2g,
    const float* __restrict__ b2, float* __restrict__ out)
{
    extern __shared__ char smg[];
    __nv_bfloat16* sBhi = (__nv_bfloat16*)(smg + SM_BHI);
    __nv_bfloat16* sBlo = (__nv_bfloat16*)(smg + SM_BLO);
    __nv_bfloat16* sAhi = (__nv_bfloat16*)(smg + SM_AHI);
    __nv_bfloat16* sAlo = (__nv_bfloat16*)(smg + SM_ALO);
    float*         sC   = (float*)(smg + SM_C);
    float*         sW1  = (float*)(smg + SM_W1);      // [3][128]
    float*         sB2  = (float*)(smg + SM_B2);
    float4*        sNbr = (float4*)(smg + SM_NBR);
    int*           sSc  = (int*)(smg + SM_SC);

    const int tid = threadIdx.x;
    const int wid = tid >> 5;

    // ---- stage W2 split-bf16 (row-major [k][n]) + W1 positional rows + b2 ----
    for (int i = tid; i < HH * HH; i += 256) {
        int k = i >> 7, n = i & 127;
        float w = W2g[i];
        __nv_bfloat16 hb = __float2bfloat16(w);
        __nv_bfloat16 lb = __float2bfloat16(w - __bfloat162float(hb));
        sBhi[k * LDA + n] = hb;
        sBlo[k * LDA + n] = lb;
    }
    for (int i = tid; i < 3 * HH; i += 256) sW1[i] = W1[64 * HH + i];   // BUGFIX: full 384
    for (int i = tid; i < HH; i += 256)     sB2[i] = b2[i];
    __syncthreads();

    // A-build assignment: row = tid>>1, col half = (tid&1)*64
    const int arow = tid >> 1;
    const int acol = (tid & 1) * 64;

    for (int g = blockIdx.x; g < NTILE; g += NBLK_G) {
        const int t0 = g * 4;

        if (tid < 128) sNbr[tid] = g_nbr[t0 * KN + tid];
        if (tid < 4)   sSc[tid]  = g_scnt[t0 + tid];
        __syncthreads();

        // ---- build A (h1) split-bf16 ----
        {
            float4 nb = sNbr[arow];
            int j = __float_as_int(nb.w);
            const float* Srow = g_S + (j >= 0 ? j : 0) * HH + acol;
            __nv_bfloat16* dh = sAhi + arow * LDA + acol;
            __nv_bfloat16* dl = sAlo + arow * LDA + acol;
#pragma unroll 4
            for (int c = 0; c < 64; c += 4) {
                float4 sv = (j >= 0) ? *(const float4*)(Srow + c)
                                     : make_float4(0.f, 0.f, 0.f, 0.f);
                float4 wx = *(const float4*)(sW1 + 0 * HH + acol + c);
                float4 wy = *(const float4*)(sW1 + 1 * HH + acol + c);
                float4 wz = *(const float4*)(sW1 + 2 * HH + acol + c);
                float v[4];
                v[0] = fmaxf(sv.x + nb.x * wx.x + nb.y * wy.x + nb.z * wz.x, 0.f);
                v[1] = fmaxf(sv.y + nb.x * wx.y + nb.y * wy.y + nb.z * wz.y, 0.f);
                v[2] = fmaxf(sv.z + nb.x * wx.z + nb.y * wy.z + nb.z * wz.z, 0.f);
                v[3] = fmaxf(sv.w + nb.x * wx.w + nb.y * wy.w + nb.z * wz.w, 0.f);
                unsigned short hs[4], ls[4];
#pragma unroll
                for (int q = 0; q < 4; q++) {
                    __nv_bfloat16 hb = __float2bfloat16(v[q]);
                    __nv_bfloat16 lb = __float2bfloat16(v[q] - __bfloat162float(hb));
                    hs[q] = __bfloat16_as_ushort(hb);
                    ls[q] = __bfloat16_as_ushort(lb);
                }
                *(uint2*)(dh + c) = make_uint2(((uint32_t)hs[1] << 16) | hs[0],
                                               ((uint32_t)hs[3] << 16) | hs[2]);
                *(uint2*)(dl + c) = make_uint2(((uint32_t)ls[1] << 16) | ls[0],
                                               ((uint32_t)ls[3] << 16) | ls[2]);
            }
        }
        __syncthreads();

        // ---- WMMA: C = Ah*Bh + Ah*Bl + Al*Bh ; warp wid owns rows 16*wid ----
        {
            wmma::fragment<wmma::accumulator, 16, 16, 16, float> acc[8];
#pragma unroll
            for (int n = 0; n < 8; n++) wmma::fill_fragment(acc[n], 0.0f);

            const int m0 = wid * 16;
#pragma unroll
            for (int k0 = 0; k0 < 8; k0++) {
                wmma::fragment<wmma::matrix_a, 16, 16, 16, __nv_bfloat16, wmma::row_major> ah, al;
                wmma::load_matrix_sync(ah, sAhi + m0 * LDA + k0 * 16, LDA);
                wmma::load_matrix_sync(al, sAlo + m0 * LDA + k0 * 16, LDA);
#pragma unroll
                for (int n = 0; n < 8; n++) {
                    wmma::fragment<wmma::matrix_b, 16, 16, 16, __nv_bfloat16, wmma::row_major> bh, bl;
                    wmma::load_matrix_sync(bh, sBhi + k0 * 16 * LDA + n * 16, LDA);
                    wmma::load_matrix_sync(bl, sBlo + k0 * 16 * LDA + n * 16, LDA);
                    wmma::mma_sync(acc[n], ah, bh, acc[n]);
                    wmma::mma_sync(acc[n], ah, bl, acc[n]);
                    wmma::mma_sync(acc[n], al, bh, acc[n]);
                }
            }
            __syncthreads();   // A reads done everywhere before C overwrites region
#pragma unroll
            for (int n = 0; n < 8; n++)
                wmma::store_matrix_sync(sC + m0 * LDC + n * 16, acc[n], LDC,
                                        wmma::mem_row_major);
        }
        __syncthreads();

        // ---- epilogue: out[t][ch] = max over valid rows of relu(C+b2) ----
#pragma unroll
        for (int i = 0; i < 2; i++) {
            int idx = tid + 256 * i;
            int tl = idx >> 7;
            int ch = idx & 127;
            int sc = sSc[tl];
            float bias = sB2[ch];
            float m = 0.0f;
            const float* crow = sC + (tl * 32) * LDC + ch;
#pragma unroll
            for (int r = 0; r < KN; r++) {
                float v = fmaxf(crow[r * LDC] + bias, 0.0f);
                m = (r < sc) ? fmaxf(m, v) : m;
            }
            out[(t0 + tl) * HH + ch] = m;
        }
        __syncthreads();   // C reads done before next tile's A build
    }
}

// ---------------------------------------------------------------------------
__global__ void k_tail(const float* __restrict__ tpos, const int* __restrict__ tb,
                       float* __restrict__ out, int mode)
{
    int i = blockIdx.x * blockDim.x + threadIdx.x;
    const int off = N_TGT * HH;
    if (i < N_TGT * 3) out[off + i] = tpos[i];
    if (mode >= 2 && i < N_TGT) out[off + N_TGT * 3 + i] = (float)tb[i];
}

// ---------------------------------------------------------------------------
extern "C" void kernel_launch(void* const* d_in, const int* in_sizes, int n_in,
                              void* d_out, int out_size)
{
    const float* srcf = (const float*)d_in[0];
    const float* srcp = (const float*)d_in[1];
    const int*   srcb = (const int*)d_in[2];
    const float* tpos = (const float*)d_in[4];
    const int*   tbat = (const int*)d_in[5];
    const float* W1   = (const float*)d_in[6];
    const float* b1   = (const float*)d_in[7];
    const float* W2   = (const float*)d_in[8];
    const float* b2   = (const float*)d_in[9];
    float* out = (float*)d_out;

    cudaFuncSetAttribute(k_gemm, cudaFuncAttributeMaxDynamicSharedMemorySize, SMEM_G);

    k_zero<<<(NCELL + 255) / 256, 256>>>();
    k_pre<<<N_SRC / 4, 128>>>(srcf, srcp, srcb, W1, b1);
    k_scan<<<1, NCELL>>>();
    k_scatter<<<N_SRC / 128, 128>>>();
    k_search<<<N_TGT, 128>>>(tpos);
    k_gemm<<<NBLK_G, 256, SMEM_G>>>(W1, W2, b2, out);

    const int base = N_TGT * HH;
    if (out_size >= base + N_TGT * 3) {
        int mode = (out_size >= base + N_TGT * 3 + N_TGT) ? 2 : 1;
        int tot = N_TGT * 3;
        k_tail<<<(tot + 255) / 256, 256>>>(tpos, tbat, out, mode);
    }
}

// round 8
// speedup vs baseline: 3.1956x; 1.1266x over previous
#include <cuda_runtime.h>
#include <cuda_bf16.h>
#include <mma.h>
#include <cstdint>

using namespace nvcuda;

#define N_SRC 8192
#define N_TGT 16384
#define DD 64
#define HH 128
#define KN 32
#define CMAX 256
#define GRID 8
#define NCELL (GRID*GRID*GRID)
#define NTILE (N_TGT / 4)          // 4096 tiles of 4 targets
#define NBLK_G 148                 // persistent GEMM blocks (1/SM)

#define LDA 136                    // bf16 leading dim (conflict-free for ldmatrix)
#define LDC 132                    // fp32 leading dim

// ---------------- device scratch ----------------
static __device__ float  g_S[N_SRC * HH];
static __device__ float4 g_spos[N_SRC];
static __device__ float  g_ss[N_SRC];
static __device__ int    g_cell[N_SRC];
static __device__ int    g_cnt[NCELL];
static __device__ int    g_fill[NCELL];
static __device__ int    g_start[NCELL + 1];
static __device__ float4 g_bp[N_SRC];
static __device__ int    g_bidx[N_SRC];
static __device__ float4 g_nbr[N_TGT * KN];   // (relx, rely, relz, bitcast j or -1)
static __device__ int    g_scnt[N_TGT];

// ---------------- k_gemm smem layout (bytes) ----------------
#define SM_BHI   0                       // 128*136*2 = 34816
#define SM_BLO   34816
#define SM_AHI   69632                   // reused as C (fp32 128x132 = 67584)
#define SM_ALO   104448
#define SM_C     69632
#define SM_W1    139264                  // 3*128*4 = 1536
#define SM_B2    140800                  // 512
#define SM_NBR   141312                  // 128*16 = 2048
#define SM_SC    143360                  // 4 ints
#define SMEM_G   143392

static __device__ __forceinline__ int cell_of(float x, float y, float z) {
    int cx = min(GRID - 1, max(0, (int)floorf(x * (float)GRID)));
    int cy = min(GRID - 1, max(0, (int)floorf(y * (float)GRID)));
    int cz = min(GRID - 1, max(0, (int)floorf(z * (float)GRID)));
    return (cz * GRID + cy) * GRID + cx;
}

// ---------------------------------------------------------------------------
__global__ void k_zero() {
    int i = blockIdx.x * blockDim.x + threadIdx.x;
    if (i < NCELL) { g_cnt[i] = 0; g_fill[i] = 0; }
}

__global__ void __launch_bounds__(128) k_pre(
    const float* __restrict__ srcf, const float* __restrict__ srcp,
    const int* __restrict__ srcb, const float* __restrict__ W1,
    const float* __restrict__ b1)
{
    const int j0 = blockIdx.x * 4;
    const int t = threadIdx.x;
    __shared__ float sx[4][DD];
    for (int i = t; i < 4 * DD; i += 128) sx[i / DD][i % DD] = srcf[j0 * DD + i];
    __syncthreads();
    float a0, a1, a2, a3;
    a0 = a1 = a2 = a3 = b1[t];
#pragma unroll
    for (int d = 0; d < DD; d++) {
        float w = W1[d * HH + t];
        a0 = fmaf(sx[0][d], w, a0);
        a1 = fmaf(sx[1][d], w, a1);
        a2 = fmaf(sx[2][d], w, a2);
        a3 = fmaf(sx[3][d], w, a3);
    }
    g_S[(j0 + 0) * HH + t] = a0;
    g_S[(j0 + 1) * HH + t] = a1;
    g_S[(j0 + 2) * HH + t] = a2;
    g_S[(j0 + 3) * HH + t] = a3;
    if (t < 4) {
        int j = j0 + t;
        float x = srcp[j * 3 + 0], y = srcp[j * 3 + 1], z = srcp[j * 3 + 2];
        g_spos[j] = make_float4(x, y, z, (float)srcb[j]);
        g_ss[j] = x * x + y * y + z * z;
        int c = cell_of(x, y, z);
        g_cell[j] = c;
        atomicAdd(&g_cnt[c], 1);
    }
}

__global__ void __launch_bounds__(NCELL) k_scan() {
    __shared__ int s[NCELL];
    int t = threadIdx.x;
    s[t] = g_cnt[t];
    __syncthreads();
#pragma unroll
    for (int off = 1; off < NCELL; off <<= 1) {
        int v = (t >= off) ? s[t - off] : 0;
        __syncthreads();
        s[t] += v;
        __syncthreads();
    }
    g_start[t + 1] = s[t];
    if (t == 0) g_start[0] = 0;
}

__global__ void __launch_bounds__(128) k_scatter() {
    int j = blockIdx.x * 128 + threadIdx.x;
    if (j >= N_SRC) return;
    int c = g_cell[j];
    int off = atomicAdd(&g_fill[c], 1);
    int dst = g_start[c] + off;
    float4 p = g_spos[j];
    g_bp[dst] = make_float4(p.x, p.y, p.z, g_ss[j]);
    g_bidx[dst] = j;
}

// ---------------------------------------------------------------------------
// search: one block per target -> neighbor list (rel, idx) + count
// ---------------------------------------------------------------------------
__global__ void __launch_bounds__(128) k_search(const float* __restrict__ tpos)
{
    __shared__ float cd2[CMAX];
    __shared__ int   cidx[CMAX];
    __shared__ int   ssel[KN];
    __shared__ int   scnt;
    __shared__ int   span_s[9], span_c[10], span_n;

    const int t = blockIdx.x;
    const int tid = threadIdx.x;

    const float tx = tpos[t * 3 + 0];
    const float ty = tpos[t * 3 + 1];
    const float tz = tpos[t * 3 + 2];
    const float tt = tx * tx + ty * ty + tz * tz;
    const float R2 = (float)(0.12 * 0.12);

    // ---- parallel span build ----
    {
        const float RM = 0.121f;
        int lx = max(0, (int)floorf((tx - RM) * (float)GRID));
        int hx = min(GRID - 1, (int)floorf((tx + RM) * (float)GRID));
        int ly = max(0, (int)floorf((ty - RM) * (float)GRID));
        int hy = min(GRID - 1, (int)floorf((ty + RM) * (float)GRID));
        int lz = max(0, (int)floorf((tz - RM) * (float)GRID));
        int hz = min(GRID - 1, (int)floorf((tz + RM) * (float)GRID));
        int nsy = hy - ly + 1;
        int ns  = nsy * (hz - lz + 1);
        if (tid == 0) { scnt = 0; span_n = ns; }
        int len = 0;
        if (tid < ns) {
            int cz = lz + tid / nsy;
            int cy = ly + tid % nsy;
            int cbase = (cz * GRID + cy) * GRID;
            int s0 = g_start[cbase + lx];
            len = g_start[cbase + hx + 1] - s0;
            span_s[tid] = s0;
        }
        if (tid < 32) {
            int v = len;
#pragma unroll
            for (int o = 1; o < 16; o <<= 1) {
                int u = __shfl_up_sync(0xffffffffu, v, o);
                if (tid >= o) v += u;
            }
            if (tid < 9) span_c[tid + 1] = v;   // inclusive scan (len=0 past ns)
            if (tid == 0) span_c[0] = 0;
        }
    }
    __syncthreads();

    {
        const int ns = span_n;
        const int T = span_c[ns];
        for (int i = tid; i < T; i += 128) {
            int sp = 0;
            while (i >= span_c[sp + 1]) sp++;
            int s = span_s[sp] + (i - span_c[sp]);
            float4 p = g_bp[s];
            float dot = tx * p.x + ty * p.y + tz * p.z;
            float d2 = (tt + p.w) - 2.0f * dot;
            if (d2 <= R2) {
                int c = atomicAdd(&scnt, 1);
                if (c < CMAX) { cd2[c] = d2; cidx[c] = g_bidx[s]; }
            }
        }
    }
    __syncthreads();

    const int C = min(scnt, CMAX);
    const int selCnt = min(C, KN);

    if (C <= KN) {
        if (tid < C) ssel[tid] = cidx[tid];
    } else {
        for (int i = tid; i < C; i += 128) {
            float di = cd2[i];
            int   ii = cidx[i];
            int r = 0;
            for (int k2 = 0; k2 < C; k2++) {
                float dk = cd2[k2];
                r += (int)((dk < di) || (dk == di && cidx[k2] < ii));
            }
            if (r < KN) ssel[r] = cidx[i];
        }
    }
    __syncthreads();

    if (tid < KN) {
        if (tid < selCnt) {
            int j = ssel[tid];
            float4 p = g_spos[j];
            g_nbr[t * KN + tid] = make_float4(p.x - tx, p.y - ty, p.z - tz,
                                              __int_as_float(j));
        } else {
            g_nbr[t * KN + tid] = make_float4(0.f, 0.f, 0.f, __int_as_float(-1));
        }
    }
    if (tid == 0) g_scnt[t] = selCnt;
}

// ---------------------------------------------------------------------------
// GEMM: persistent; per tile 4 targets x 32 nbrs; split-bf16 WMMA (HMMA)
// warp grid 4m x 2n: warp tile 32 rows x 64 cols -> 1.5x less fragment traffic
// ---------------------------------------------------------------------------
__global__ void __launch_bounds__(256) k_gemm(
    const float* __restrict__ W1, const float* __restrict__ W2g,
    const float* __restrict__ b2, float* __restrict__ out)
{
    extern __shared__ char smg[];
    __nv_bfloat16* sBhi = (__nv_bfloat16*)(smg + SM_BHI);
    __nv_bfloat16* sBlo = (__nv_bfloat16*)(smg + SM_BLO);
    __nv_bfloat16* sAhi = (__nv_bfloat16*)(smg + SM_AHI);
    __nv_bfloat16* sAlo = (__nv_bfloat16*)(smg + SM_ALO);
    float*         sC   = (float*)(smg + SM_C);
    float*         sW1  = (float*)(smg + SM_W1);      // [3][128]
    float*         sB2  = (float*)(smg + SM_B2);
    float4*        sNbr = (float4*)(smg + SM_NBR);
    int*           sSc  = (int*)(smg + SM_SC);

    const int tid = threadIdx.x;
    const int wid = tid >> 5;

    // ---- stage W2 split-bf16 (row-major [k][n]) + W1 positional rows + b2 ----
    for (int i = tid; i < HH * HH; i += 256) {
        int k = i >> 7, n = i & 127;
        float w = W2g[i];
        __nv_bfloat16 hb = __float2bfloat16(w);
        __nv_bfloat16 lb = __float2bfloat16(w - __bfloat162float(hb));
        sBhi[k * LDA + n] = hb;
        sBlo[k * LDA + n] = lb;
    }
    for (int i = tid; i < 3 * HH; i += 256) sW1[i] = W1[64 * HH + i];
    for (int i = tid; i < HH; i += 256)     sB2[i] = b2[i];
    __syncthreads();

    // A-build assignment: row = tid>>1, col half = (tid&1)*64
    const int arow = tid >> 1;
    const int acol = (tid & 1) * 64;

    // warp tiling: 4m x 2n
    const int wm = wid & 3;          // row group: rows 32*wm .. +32
    const int wn = wid >> 2;         // col group: cols 64*wn .. +64
    const int mA = 32 * wm;
    const int nB = 64 * wn;

    for (int g = blockIdx.x; g < NTILE; g += NBLK_G) {
        const int t0 = g * 4;

        if (tid < 128) sNbr[tid] = g_nbr[t0 * KN + tid];
        if (tid < 4)   sSc[tid]  = g_scnt[t0 + tid];
        __syncthreads();

        // ---- build A (h1) split-bf16 ----
        {
            float4 nb = sNbr[arow];
            int j = __float_as_int(nb.w);
            const float* Srow = g_S + (j >= 0 ? j : 0) * HH + acol;
            __nv_bfloat16* dh = sAhi + arow * LDA + acol;
            __nv_bfloat16* dl = sAlo + arow * LDA + acol;
#pragma unroll 4
            for (int c = 0; c < 64; c += 4) {
                float4 sv = (j >= 0) ? *(const float4*)(Srow + c)
                                     : make_float4(0.f, 0.f, 0.f, 0.f);
                float4 wx = *(const float4*)(sW1 + 0 * HH + acol + c);
                float4 wy = *(const float4*)(sW1 + 1 * HH + acol + c);
                float4 wz = *(const float4*)(sW1 + 2 * HH + acol + c);
                float v[4];
                v[0] = fmaxf(sv.x + nb.x * wx.x + nb.y * wy.x + nb.z * wz.x, 0.f);
                v[1] = fmaxf(sv.y + nb.x * wx.y + nb.y * wy.y + nb.z * wz.y, 0.f);
                v[2] = fmaxf(sv.z + nb.x * wx.z + nb.y * wy.z + nb.z * wz.z, 0.f);
                v[3] = fmaxf(sv.w + nb.x * wx.w + nb.y * wy.w + nb.z * wz.w, 0.f);
                unsigned short hs[4], ls[4];
#pragma unroll
                for (int q = 0; q < 4; q++) {
                    __nv_bfloat16 hb = __float2bfloat16(v[q]);
                    __nv_bfloat16 lb = __float2bfloat16(v[q] - __bfloat162float(hb));
                    hs[q] = __bfloat16_as_ushort(hb);
                    ls[q] = __bfloat16_as_ushort(lb);
                }
                *(uint2*)(dh + c) = make_uint2(((uint32_t)hs[1] << 16) | hs[0],
                                               ((uint32_t)hs[3] << 16) | hs[2]);
                *(uint2*)(dl + c) = make_uint2(((uint32_t)ls[1] << 16) | ls[0],
                                               ((uint32_t)ls[3] << 16) | ls[2]);
            }
        }
        __syncthreads();

        // ---- WMMA: C = Ah*Bh + Ah*Bl + Al*Bh ; warp tile 32x64 ----
        {
            wmma::fragment<wmma::accumulator, 16, 16, 16, float> acc[2][4];
#pragma unroll
            for (int i = 0; i < 2; i++)
#pragma unroll
                for (int n = 0; n < 4; n++) wmma::fill_fragment(acc[i][n], 0.0f);

#pragma unroll
            for (int k0 = 0; k0 < 8; k0++) {
                wmma::fragment<wmma::matrix_a, 16, 16, 16, __nv_bfloat16, wmma::row_major> ah0, al0, ah1, al1;
                wmma::load_matrix_sync(ah0, sAhi + (mA +  0) * LDA + k0 * 16, LDA);
                wmma::load_matrix_sync(al0, sAlo + (mA +  0) * LDA + k0 * 16, LDA);
                wmma::load_matrix_sync(ah1, sAhi + (mA + 16) * LDA + k0 * 16, LDA);
                wmma::load_matrix_sync(al1, sAlo + (mA + 16) * LDA + k0 * 16, LDA);
#pragma unroll
                for (int n = 0; n < 4; n++) {
                    wmma::fragment<wmma::matrix_b, 16, 16, 16, __nv_bfloat16, wmma::row_major> bh, bl;
                    wmma::load_matrix_sync(bh, sBhi + k0 * 16 * LDA + nB + n * 16, LDA);
                    wmma::load_matrix_sync(bl, sBlo + k0 * 16 * LDA + nB + n * 16, LDA);
                    wmma::mma_sync(acc[0][n], ah0, bh, acc[0][n]);
                    wmma::mma_sync(acc[0][n], ah0, bl, acc[0][n]);
                    wmma::mma_sync(acc[0][n], al0, bh, acc[0][n]);
                    wmma::mma_sync(acc[1][n], ah1, bh, acc[1][n]);
                    wmma::mma_sync(acc[1][n], ah1, bl, acc[1][n]);
                    wmma::mma_sync(acc[1][n], al1, bh, acc[1][n]);
                }
            }
            __syncthreads();   // A reads done everywhere before C overwrites region
#pragma unroll
            for (int i = 0; i < 2; i++)
#pragma unroll
                for (int n = 0; n < 4; n++)
                    wmma::store_matrix_sync(sC + (mA + i * 16) * LDC + nB + n * 16,
                                            acc[i][n], LDC, wmma::mem_row_major);
        }
        __syncthreads();

        // ---- epilogue: out[t][ch] = max over valid rows of relu(C+b2) ----
#pragma unroll
        for (int i = 0; i < 2; i++) {
            int idx = tid + 256 * i;
            int tl = idx >> 7;
            int ch = idx & 127;
            int sc = sSc[tl];
            float bias = sB2[ch];
            float m = 0.0f;
            const float* crow = sC + (tl * 32) * LDC + ch;
#pragma unroll
            for (int r = 0; r < KN; r++) {
                float v = fmaxf(crow[r * LDC] + bias, 0.0f);
                m = (r < sc) ? fmaxf(m, v) : m;
            }
            out[(t0 + tl) * HH + ch] = m;
        }
        __syncthreads();   // C reads done before next tile's A build
    }
}

// ---------------------------------------------------------------------------
__global__ void k_tail(const float* __restrict__ tpos, const int* __restrict__ tb,
                       float* __restrict__ out, int mode)
{
    int i = blockIdx.x * blockDim.x + threadIdx.x;
    const int off = N_TGT * HH;
    if (i < N_TGT * 3) out[off + i] = tpos[i];
    if (mode >= 2 && i < N_TGT) out[off + N_TGT * 3 + i] = (float)tb[i];
}

// ---------------------------------------------------------------------------
extern "C" void kernel_launch(void* const* d_in, const int* in_sizes, int n_in,
                              void* d_out, int out_size)
{
    const float* srcf = (const float*)d_in[0];
    const float* srcp = (const float*)d_in[1];
    const int*   srcb = (const int*)d_in[2];
    const float* tpos = (const float*)d_in[4];
    const int*   tbat = (const int*)d_in[5];
    const float* W1   = (const float*)d_in[6];
    const float* b1   = (const float*)d_in[7];
    const float* W2   = (const float*)d_in[8];
    const float* b2   = (const float*)d_in[9];
    float* out = (float*)d_out;

    cudaFuncSetAttribute(k_gemm, cudaFuncAttributeMaxDynamicSharedMemorySize, SMEM_G);

    k_zero<<<(NCELL + 255) / 256, 256>>>();
    k_pre<<<N_SRC / 4, 128>>>(srcf, srcp, srcb, W1, b1);
    k_scan<<<1, NCELL>>>();
    k_scatter<<<N_SRC / 128, 128>>>();
    k_search<<<N_TGT, 128>>>(tpos);
    k_gemm<<<NBLK_G, 256, SMEM_G>>>(W1, W2, b2, out);

    const int base = N_TGT * HH;
    if (out_size >= base + N_TGT * 3) {
        int mode = (out_size >= base + N_TGT * 3 + N_TGT) ? 2 : 1;
        int tot = N_TGT * 3;
        k_tail<<<(tot + 255) / 256, 256>>>(tpos, tbat, out, mode);
    }
}

// round 9
// speedup vs baseline: 3.8056x; 1.1909x over previous
#include <cuda_runtime.h>
#include <cuda_bf16.h>
#include <cstdint>

#define N_SRC 8192
#define N_TGT 16384
#define DD 64
#define HH 128
#define KN 32
#define CMAX 256
#define GRID 8
#define NCELL (GRID*GRID*GRID)
#define NTILE (N_TGT / 4)          // 4096 tiles of 4 targets
#define NBLK_G 148                 // persistent GEMM blocks (1/SM)

#define LDA 136                    // bf16 leading dim (conflict-free ldmatrix)

// ---------------- device scratch ----------------
static __device__ float  g_S[N_SRC * HH];
static __device__ float4 g_spos[N_SRC];
static __device__ float  g_ss[N_SRC];
static __device__ int    g_cell[N_SRC];
static __device__ int    g_cnt[NCELL];
static __device__ int    g_fill[NCELL];
static __device__ int    g_start[NCELL + 1];
static __device__ float4 g_bp[N_SRC];
static __device__ int    g_bidx[N_SRC];
static __device__ float4 g_nbr[N_TGT * KN];   // (relx, rely, relz, bitcast j or -1)
static __device__ int    g_scnt[N_TGT];

// ---------------- k_gemm smem layout (bytes) ----------------
#define SM_BHI   0                       // 128*136*2 = 34816
#define SM_BLO   34816
#define SM_AHI   69632
#define SM_ALO   104448
#define SM_W1    139264                  // 3*128*4 = 1536
#define SM_B2    140800                  // 512
#define SM_NBR   141312                  // 128*16 = 2048
#define SM_SC    143360                  // 4 ints
#define SMEM_G   143392

static __device__ __forceinline__ uint32_t smem_u32(const void* p) {
    uint32_t a;
    asm("{ .reg .u64 t; cvta.to.shared.u64 t, %1; cvt.u32.u64 %0, t; }" : "=r"(a) : "l"(p));
    return a;
}

static __device__ __forceinline__ void ldsm_x4(uint32_t* r, uint32_t addr) {
    asm volatile("ldmatrix.sync.aligned.m8n8.x4.shared.b16 {%0,%1,%2,%3}, [%4];"
                 : "=r"(r[0]), "=r"(r[1]), "=r"(r[2]), "=r"(r[3]) : "r"(addr));
}
static __device__ __forceinline__ void ldsm_x2t(uint32_t* r, uint32_t addr) {
    asm volatile("ldmatrix.sync.aligned.m8n8.x2.trans.shared.b16 {%0,%1}, [%2];"
                 : "=r"(r[0]), "=r"(r[1]) : "r"(addr));
}
static __device__ __forceinline__ void mma_bf16(float* d, const uint32_t* a, const uint32_t* b) {
    asm volatile("mma.sync.aligned.m16n8k16.row.col.f32.bf16.bf16.f32 "
                 "{%0,%1,%2,%3}, {%4,%5,%6,%7}, {%8,%9}, {%0,%1,%2,%3};"
                 : "+f"(d[0]), "+f"(d[1]), "+f"(d[2]), "+f"(d[3])
                 : "r"(a[0]), "r"(a[1]), "r"(a[2]), "r"(a[3]), "r"(b[0]), "r"(b[1]));
}

static __device__ __forceinline__ int cell_of(float x, float y, float z) {
    int cx = min(GRID - 1, max(0, (int)floorf(x * (float)GRID)));
    int cy = min(GRID - 1, max(0, (int)floorf(y * (float)GRID)));
    int cz = min(GRID - 1, max(0, (int)floorf(z * (float)GRID)));
    return (cz * GRID + cy) * GRID + cx;
}

// ---------------------------------------------------------------------------
__global__ void k_zero() {
    int i = blockIdx.x * blockDim.x + threadIdx.x;
    if (i < NCELL) { g_cnt[i] = 0; g_fill[i] = 0; }
}

__global__ void __launch_bounds__(128) k_pre(
    const float* __restrict__ srcf, const float* __restrict__ srcp,
    const int* __restrict__ srcb, const float* __restrict__ W1,
    const float* __restrict__ b1)
{
    const int j0 = blockIdx.x * 4;
    const int t = threadIdx.x;
    __shared__ float sx[4][DD];
    for (int i = t; i < 4 * DD; i += 128) sx[i / DD][i % DD] = srcf[j0 * DD + i];
    __syncthreads();
    float a0, a1, a2, a3;
    a0 = a1 = a2 = a3 = b1[t];
#pragma unroll
    for (int d = 0; d < DD; d++) {
        float w = W1[d * HH + t];
        a0 = fmaf(sx[0][d], w, a0);
        a1 = fmaf(sx[1][d], w, a1);
        a2 = fmaf(sx[2][d], w, a2);
        a3 = fmaf(sx[3][d], w, a3);
    }
    g_S[(j0 + 0) * HH + t] = a0;
    g_S[(j0 + 1) * HH + t] = a1;
    g_S[(j0 + 2) * HH + t] = a2;
    g_S[(j0 + 3) * HH + t] = a3;
    if (t < 4) {
        int j = j0 + t;
        float x = srcp[j * 3 + 0], y = srcp[j * 3 + 1], z = srcp[j * 3 + 2];
        g_spos[j] = make_float4(x, y, z, (float)srcb[j]);
        g_ss[j] = x * x + y * y + z * z;
        int c = cell_of(x, y, z);
        g_cell[j] = c;
        atomicAdd(&g_cnt[c], 1);
    }
}

__global__ void __launch_bounds__(NCELL) k_scan() {
    __shared__ int s[NCELL];
    int t = threadIdx.x;
    s[t] = g_cnt[t];
    __syncthreads();
#pragma unroll
    for (int off = 1; off < NCELL; off <<= 1) {
        int v = (t >= off) ? s[t - off] : 0;
        __syncthreads();
        s[t] += v;
        __syncthreads();
    }
    g_start[t + 1] = s[t];
    if (t == 0) g_start[0] = 0;
}

__global__ void __launch_bounds__(128) k_scatter() {
    int j = blockIdx.x * 128 + threadIdx.x;
    if (j >= N_SRC) return;
    int c = g_cell[j];
    int off = atomicAdd(&g_fill[c], 1);
    int dst = g_start[c] + off;
    float4 p = g_spos[j];
    g_bp[dst] = make_float4(p.x, p.y, p.z, g_ss[j]);
    g_bidx[dst] = j;
}

// ---------------------------------------------------------------------------
// search: one block per target -> neighbor list (rel, idx) + count
// ---------------------------------------------------------------------------
__global__ void __launch_bounds__(128) k_search(const float* __restrict__ tpos)
{
    __shared__ float cd2[CMAX];
    __shared__ int   cidx[CMAX];
    __shared__ int   ssel[KN];
    __shared__ int   scnt;
    __shared__ int   span_s[9], span_c[10], span_n;

    const int t = blockIdx.x;
    const int tid = threadIdx.x;

    const float tx = tpos[t * 3 + 0];
    const float ty = tpos[t * 3 + 1];
    const float tz = tpos[t * 3 + 2];
    const float tt = tx * tx + ty * ty + tz * tz;
    const float R2 = (float)(0.12 * 0.12);

    // ---- parallel span build ----
    {
        const float RM = 0.121f;
        int lx = max(0, (int)floorf((tx - RM) * (float)GRID));
        int hx = min(GRID - 1, (int)floorf((tx + RM) * (float)GRID));
        int ly = max(0, (int)floorf((ty - RM) * (float)GRID));
        int hy = min(GRID - 1, (int)floorf((ty + RM) * (float)GRID));
        int lz = max(0, (int)floorf((tz - RM) * (float)GRID));
        int hz = min(GRID - 1, (int)floorf((tz + RM) * (float)GRID));
        int nsy = hy - ly + 1;
        int ns  = nsy * (hz - lz + 1);
        if (tid == 0) { scnt = 0; span_n = ns; }
        int len = 0;
        if (tid < ns) {
            int cz = lz + tid / nsy;
            int cy = ly + tid % nsy;
            int cbase = (cz * GRID + cy) * GRID;
            int s0 = g_start[cbase + lx];
            len = g_start[cbase + hx + 1] - s0;
            span_s[tid] = s0;
        }
        if (tid < 32) {
            int v = len;
#pragma unroll
            for (int o = 1; o < 16; o <<= 1) {
                int u = __shfl_up_sync(0xffffffffu, v, o);
                if (tid >= o) v += u;
            }
            if (tid < 9) span_c[tid + 1] = v;
            if (tid == 0) span_c[0] = 0;
        }
    }
    __syncthreads();

    {
        const int ns = span_n;
        const int T = span_c[ns];
        for (int i = tid; i < T; i += 128) {
            int sp = 0;
            while (i >= span_c[sp + 1]) sp++;
            int s = span_s[sp] + (i - span_c[sp]);
            float4 p = g_bp[s];
            float dot = tx * p.x + ty * p.y + tz * p.z;
            float d2 = (tt + p.w) - 2.0f * dot;
            if (d2 <= R2) {
                int c = atomicAdd(&scnt, 1);
                if (c < CMAX) { cd2[c] = d2; cidx[c] = g_bidx[s]; }
            }
        }
    }
    __syncthreads();

    const int C = min(scnt, CMAX);
    const int selCnt = min(C, KN);

    if (C <= KN) {
        if (tid < C) ssel[tid] = cidx[tid];
    } else {
        for (int i = tid; i < C; i += 128) {
            float di = cd2[i];
            int   ii = cidx[i];
            int r = 0;
            for (int k2 = 0; k2 < C; k2++) {
                float dk = cd2[k2];
                r += (int)((dk < di) || (dk == di && cidx[k2] < ii));
            }
            if (r < KN) ssel[r] = cidx[i];
        }
    }
    __syncthreads();

    if (tid < KN) {
        if (tid < selCnt) {
            int j = ssel[tid];
            float4 p = g_spos[j];
            g_nbr[t * KN + tid] = make_float4(p.x - tx, p.y - ty, p.z - tz,
                                              __int_as_float(j));
        } else {
            g_nbr[t * KN + tid] = make_float4(0.f, 0.f, 0.f, __int_as_float(-1));
        }
    }
    if (tid == 0) g_scnt[t] = selCnt;
}

// ---------------------------------------------------------------------------
// GEMM: persistent; per tile 4 targets x 32 nbrs; split-bf16 raw mma.sync
// register-domain epilogue (no C smem round trip)
// ---------------------------------------------------------------------------
__global__ void __launch_bounds__(256) k_gemm(
    const float* __restrict__ W1, const float* __restrict__ W2g,
    const float* __restrict__ b2, float* __restrict__ out)
{
    extern __shared__ char smg[];
    __nv_bfloat16* sBhi = (__nv_bfloat16*)(smg + SM_BHI);
    __nv_bfloat16* sBlo = (__nv_bfloat16*)(smg + SM_BLO);
    __nv_bfloat16* sAhi = (__nv_bfloat16*)(smg + SM_AHI);
    __nv_bfloat16* sAlo = (__nv_bfloat16*)(smg + SM_ALO);
    float*         sW1  = (float*)(smg + SM_W1);      // [3][128]
    float*         sB2  = (float*)(smg + SM_B2);
    float4*        sNbr = (float4*)(smg + SM_NBR);
    int*           sSc  = (int*)(smg + SM_SC);

    const int tid  = threadIdx.x;
    const int wid  = tid >> 5;
    const int lane = tid & 31;

    // ---- stage W2 split-bf16 (row-major [k][n]) + W1 positional rows + b2 ----
    for (int i = tid; i < HH * HH; i += 256) {
        int k = i >> 7, n = i & 127;
        float w = W2g[i];
        __nv_bfloat16 hb = __float2bfloat16(w);
        __nv_bfloat16 lb = __float2bfloat16(w - __bfloat162float(hb));
        sBhi[k * LDA + n] = hb;
        sBlo[k * LDA + n] = lb;
    }
    for (int i = tid; i < 3 * HH; i += 256) sW1[i] = W1[64 * HH + i];
    for (int i = tid; i < HH; i += 256)     sB2[i] = b2[i];
    __syncthreads();

    // A-build assignment: row = tid>>1, col half = (tid&1)*64
    const int arow = tid >> 1;
    const int acol = (tid & 1) * 64;

    // warp tiling: 4m x 2n (warp tile 32 rows x 64 cols); wm == target in tile
    const int wm = wid & 3;
    const int wn = wid >> 2;
    const int mA = 32 * wm;
    const int nB = 64 * wn;

    const uint32_t uAhi = smem_u32(sAhi), uAlo = smem_u32(sAlo);
    const uint32_t uBhi = smem_u32(sBhi), uBlo = smem_u32(sBlo);

    // per-thread ldmatrix offsets (bytes)
    const int l15 = lane & 15;
    const uint32_t aoff0 = (uint32_t)(((mA + l15) * LDA + (lane >> 4) * 8) * 2);
    const uint32_t aoff1 = aoff0 + 16 * LDA * 2;
    const uint32_t boff  = (uint32_t)((l15 * LDA + nB) * 2);
    const uint32_t kstep = 16 * LDA * 2;

    // per-thread bias registers (cols fixed across tiles)
    const int tid4 = lane & 3;
    const int g4   = lane >> 2;
    float bias0[8], bias1[8];
#pragma unroll
    for (int nt = 0; nt < 8; nt++) {
        int c = nB + nt * 8 + tid4 * 2;
        bias0[nt] = sB2[c];
        bias1[nt] = sB2[c + 1];
    }

    for (int g = blockIdx.x; g < NTILE; g += NBLK_G) {
        const int t0 = g * 4;

        if (tid < 128) sNbr[tid] = g_nbr[t0 * KN + tid];
        if (tid < 4)   sSc[tid]  = g_scnt[t0 + tid];
        __syncthreads();

        const int sc = sSc[wm];     // hoist before post-MMA barrier (race-free)

        // ---- build A (h1) split-bf16 ----
        {
            float4 nb = sNbr[arow];
            int j = __float_as_int(nb.w);
            const float* Srow = g_S + (j >= 0 ? j : 0) * HH + acol;
            __nv_bfloat16* dh = sAhi + arow * LDA + acol;
            __nv_bfloat16* dl = sAlo + arow * LDA + acol;
#pragma unroll 4
            for (int c = 0; c < 64; c += 4) {
                float4 sv = (j >= 0) ? *(const float4*)(Srow + c)
                                     : make_float4(0.f, 0.f, 0.f, 0.f);
                float4 wx = *(const float4*)(sW1 + 0 * HH + acol + c);
                float4 wy = *(const float4*)(sW1 + 1 * HH + acol + c);
                float4 wz = *(const float4*)(sW1 + 2 * HH + acol + c);
                float v[4];
                v[0] = fmaxf(sv.x + nb.x * wx.x + nb.y * wy.x + nb.z * wz.x, 0.f);
                v[1] = fmaxf(sv.y + nb.x * wx.y + nb.y * wy.y + nb.z * wz.y, 0.f);
                v[2] = fmaxf(sv.z + nb.x * wx.z + nb.y * wy.z + nb.z * wz.z, 0.f);
                v[3] = fmaxf(sv.w + nb.x * wx.w + nb.y * wy.w + nb.z * wz.w, 0.f);
                unsigned short hs[4], ls[4];
#pragma unroll
                for (int q = 0; q < 4; q++) {
                    __nv_bfloat16 hb = __float2bfloat16(v[q]);
                    __nv_bfloat16 lb = __float2bfloat16(v[q] - __bfloat162float(hb));
                    hs[q] = __bfloat16_as_ushort(hb);
                    ls[q] = __bfloat16_as_ushort(lb);
                }
                *(uint2*)(dh + c) = make_uint2(((uint32_t)hs[1] << 16) | hs[0],
                                               ((uint32_t)hs[3] << 16) | hs[2]);
                *(uint2*)(dl + c) = make_uint2(((uint32_t)ls[1] << 16) | ls[0],
                                               ((uint32_t)ls[3] << 16) | ls[2]);
            }
        }
        __syncthreads();

        // ---- mma: D = bias + Ah*Bh + Ah*Bl + Al*Bh ----
        float d[2][8][4];
#pragma unroll
        for (int mt = 0; mt < 2; mt++)
#pragma unroll
            for (int nt = 0; nt < 8; nt++) {
                d[mt][nt][0] = bias0[nt];
                d[mt][nt][1] = bias1[nt];
                d[mt][nt][2] = bias0[nt];
                d[mt][nt][3] = bias1[nt];
            }

        uint32_t ah0[4], al0[4], ah1[4], al1[4], bh[2], bl[2];
#pragma unroll
        for (int k0 = 0; k0 < 8; k0++) {
            const uint32_t ka = (uint32_t)(k0 * 32);
            ldsm_x4(ah0, uAhi + aoff0 + ka);
            ldsm_x4(al0, uAlo + aoff0 + ka);
            ldsm_x4(ah1, uAhi + aoff1 + ka);
            ldsm_x4(al1, uAlo + aoff1 + ka);
            const uint32_t kb = (uint32_t)(k0 * kstep);
#pragma unroll
            for (int nt = 0; nt < 8; nt++) {
                ldsm_x2t(bh, uBhi + boff + kb + nt * 16);
                ldsm_x2t(bl, uBlo + boff + kb + nt * 16);
                mma_bf16(d[0][nt], ah0, bh);
                mma_bf16(d[0][nt], ah0, bl);
                mma_bf16(d[0][nt], al0, bh);
                mma_bf16(d[1][nt], ah1, bh);
                mma_bf16(d[1][nt], ah1, bl);
                mma_bf16(d[1][nt], al1, bh);
            }
        }
        __syncthreads();   // A reads done before next tile's A build

        // ---- register epilogue: masked relu-max over rows, shfl-reduce ----
        const bool m0 = g4      < sc;
        const bool m1 = g4 + 8  < sc;
        const bool m2 = g4 + 16 < sc;
        const bool m3 = g4 + 24 < sc;
        const int tO = (t0 + wm) * HH + nB;
#pragma unroll
        for (int nt = 0; nt < 8; nt++) {
            float v0 = 0.f, v1 = 0.f;   // 0-floor == relu + mask + empty case
            if (m0) { v0 = fmaxf(v0, d[0][nt][0]); v1 = fmaxf(v1, d[0][nt][1]); }
            if (m1) { v0 = fmaxf(v0, d[0][nt][2]); v1 = fmaxf(v1, d[0][nt][3]); }
            if (m2) { v0 = fmaxf(v0, d[1][nt][0]); v1 = fmaxf(v1, d[1][nt][1]); }
            if (m3) { v0 = fmaxf(v0, d[1][nt][2]); v1 = fmaxf(v1, d[1][nt][3]); }
#pragma unroll
            for (int o = 4; o < 32; o <<= 1) {
                v0 = fmaxf(v0, __shfl_xor_sync(0xffffffffu, v0, o));
                v1 = fmaxf(v1, __shfl_xor_sync(0xffffffffu, v1, o));
            }
            if (lane < 4)
                *(float2*)(out + tO + nt * 8 + lane * 2) = make_float2(v0, v1);
        }
    }
}

// ---------------------------------------------------------------------------
__global__ void k_tail(const float* __restrict__ tpos, const int* __restrict__ tb,
                       float* __restrict__ out, int mode)
{
    int i = blockIdx.x * blockDim.x + threadIdx.x;
    const int off = N_TGT * HH;
    if (i < N_TGT * 3) out[off + i] = tpos[i];
    if (mode >= 2 && i < N_TGT) out[off + N_TGT * 3 + i] = (float)tb[i];
}

// ---------------------------------------------------------------------------
extern "C" void kernel_launch(void* const* d_in, const int* in_sizes, int n_in,
                              void* d_out, int out_size)
{
    const float* srcf = (const float*)d_in[0];
    const float* srcp = (const float*)d_in[1];
    const int*   srcb = (const int*)d_in[2];
    const float* tpos = (const float*)d_in[4];
    const int*   tbat = (const int*)d_in[5];
    const float* W1   = (const float*)d_in[6];
    const float* b1   = (const float*)d_in[7];
    const float* W2   = (const float*)d_in[8];
    const float* b2   = (const float*)d_in[9];
    float* out = (float*)d_out;

    cudaFuncSetAttribute(k_gemm, cudaFuncAttributeMaxDynamicSharedMemorySize, SMEM_G);

    k_zero<<<(NCELL + 255) / 256, 256>>>();
    k_pre<<<N_SRC / 4, 128>>>(srcf, srcp, srcb, W1, b1);
    k_scan<<<1, NCELL>>>();
    k_scatter<<<N_SRC / 128, 128>>>();
    k_search<<<N_TGT, 128>>>(tpos);
    k_gemm<<<NBLK_G, 256, SMEM_G>>>(W1, W2, b2, out);

    const int base = N_TGT * HH;
    if (out_size >= base + N_TGT * 3) {
        int mode = (out_size >= base + N_TGT * 3 + N_TGT) ? 2 : 1;
        int tot = N_TGT * 3;
        k_tail<<<(tot + 255) / 256, 256>>>(tpos, tbat, out, mode);
    }
}

// round 10
// speedup vs baseline: 3.9868x; 1.0476x over previous
#include <cuda_runtime.h>
#include <cuda_bf16.h>
#include <cstdint>

#define N_SRC 8192
#define N_TGT 16384
#define DD 64
#define HH 128
#define KN 32
#define CMAX 256
#define GRID 8
#define NCELL (GRID*GRID*GRID)
#define TPT 8                      // targets per GEMM tile (M = 256)
#define NTILE (N_TGT / TPT)        // 2048 tiles
#define NBLK_G 148                 // persistent GEMM blocks (1/SM)

#define LDA 136                    // bf16 leading dim (conflict-free ldmatrix)

// ---------------- device scratch ----------------
static __device__ float  g_S[N_SRC * HH];
static __device__ float4 g_spos[N_SRC];
static __device__ float  g_ss[N_SRC];
static __device__ int    g_cell[N_SRC];
static __device__ int    g_cnt[NCELL];
static __device__ int    g_fill[NCELL];
static __device__ int    g_start[NCELL + 1];
static __device__ float4 g_bp[N_SRC];
static __device__ int    g_bidx[N_SRC];
static __device__ float4 g_nbr[N_TGT * KN];   // (relx, rely, relz, bitcast j or -1)
static __device__ int    g_scnt[N_TGT];

// ---------------- k_gemm smem layout (bytes) ----------------
#define SM_BHI   0                       // 128*136*2 = 34816
#define SM_BLO   34816
#define SM_AHI   69632                   // 256*136*2 = 69632
#define SM_ALO   139264
#define SM_W1    208896                  // 3*128*4 = 1536
#define SM_B2    210432                  // 512
#define SM_NBR   210944                  // 256*16 = 4096
#define SM_SC    215040                  // 8 ints
#define SMEM_G   215072

static __device__ __forceinline__ uint32_t smem_u32(const void* p) {
    uint32_t a;
    asm("{ .reg .u64 t; cvta.to.shared.u64 t, %1; cvt.u32.u64 %0, t; }" : "=r"(a) : "l"(p));
    return a;
}

static __device__ __forceinline__ void ldsm_x4(uint32_t* r, uint32_t addr) {
    asm volatile("ldmatrix.sync.aligned.m8n8.x4.shared.b16 {%0,%1,%2,%3}, [%4];"
                 : "=r"(r[0]), "=r"(r[1]), "=r"(r[2]), "=r"(r[3]) : "r"(addr));
}
static __device__ __forceinline__ void ldsm_x2t(uint32_t* r, uint32_t addr) {
    asm volatile("ldmatrix.sync.aligned.m8n8.x2.trans.shared.b16 {%0,%1}, [%2];"
                 : "=r"(r[0]), "=r"(r[1]) : "r"(addr));
}
static __device__ __forceinline__ void mma_bf16(float* d, const uint32_t* a, const uint32_t* b) {
    asm volatile("mma.sync.aligned.m16n8k16.row.col.f32.bf16.bf16.f32 "
                 "{%0,%1,%2,%3}, {%4,%5,%6,%7}, {%8,%9}, {%0,%1,%2,%3};"
                 : "+f"(d[0]), "+f"(d[1]), "+f"(d[2]), "+f"(d[3])
                 : "r"(a[0]), "r"(a[1]), "r"(a[2]), "r"(a[3]), "r"(b[0]), "r"(b[1]));
}

static __device__ __forceinline__ int cell_of(float x, float y, float z) {
    int cx = min(GRID - 1, max(0, (int)floorf(x * (float)GRID)));
    int cy = min(GRID - 1, max(0, (int)floorf(y * (float)GRID)));
    int cz = min(GRID - 1, max(0, (int)floorf(z * (float)GRID)));
    return (cz * GRID + cy) * GRID + cx;
}

// ---------------------------------------------------------------------------
__global__ void k_zero() {
    int i = blockIdx.x * blockDim.x + threadIdx.x;
    if (i < NCELL) { g_cnt[i] = 0; g_fill[i] = 0; }
}

__global__ void __launch_bounds__(128) k_pre(
    const float* __restrict__ srcf, const float* __restrict__ srcp,
    const int* __restrict__ srcb, const float* __restrict__ W1,
    const float* __restrict__ b1)
{
    const int j0 = blockIdx.x * 4;
    const int t = threadIdx.x;
    __shared__ float sx[4][DD];
    for (int i = t; i < 4 * DD; i += 128) sx[i / DD][i % DD] = srcf[j0 * DD + i];
    __syncthreads();
    float a0, a1, a2, a3;
    a0 = a1 = a2 = a3 = b1[t];
#pragma unroll
    for (int d = 0; d < DD; d++) {
        float w = W1[d * HH + t];
        a0 = fmaf(sx[0][d], w, a0);
        a1 = fmaf(sx[1][d], w, a1);
        a2 = fmaf(sx[2][d], w, a2);
        a3 = fmaf(sx[3][d], w, a3);
    }
    g_S[(j0 + 0) * HH + t] = a0;
    g_S[(j0 + 1) * HH + t] = a1;
    g_S[(j0 + 2) * HH + t] = a2;
    g_S[(j0 + 3) * HH + t] = a3;
    if (t < 4) {
        int j = j0 + t;
        float x = srcp[j * 3 + 0], y = srcp[j * 3 + 1], z = srcp[j * 3 + 2];
        g_spos[j] = make_float4(x, y, z, (float)srcb[j]);
        g_ss[j] = x * x + y * y + z * z;
        int c = cell_of(x, y, z);
        g_cell[j] = c;
        atomicAdd(&g_cnt[c], 1);
    }
}

__global__ void __launch_bounds__(NCELL) k_scan() {
    __shared__ int s[NCELL];
    int t = threadIdx.x;
    s[t] = g_cnt[t];
    __syncthreads();
#pragma unroll
    for (int off = 1; off < NCELL; off <<= 1) {
        int v = (t >= off) ? s[t - off] : 0;
        __syncthreads();
        s[t] += v;
        __syncthreads();
    }
    g_start[t + 1] = s[t];
    if (t == 0) g_start[0] = 0;
}

__global__ void __launch_bounds__(128) k_scatter() {
    int j = blockIdx.x * 128 + threadIdx.x;
    if (j >= N_SRC) return;
    int c = g_cell[j];
    int off = atomicAdd(&g_fill[c], 1);
    int dst = g_start[c] + off;
    float4 p = g_spos[j];
    g_bp[dst] = make_float4(p.x, p.y, p.z, g_ss[j]);
    g_bidx[dst] = j;
}

// ---------------------------------------------------------------------------
// search: one block per target -> neighbor list (rel, idx) + count
// ---------------------------------------------------------------------------
__global__ void __launch_bounds__(128) k_search(const float* __restrict__ tpos)
{
    __shared__ float cd2[CMAX];
    __shared__ int   cidx[CMAX];
    __shared__ int   ssel[KN];
    __shared__ int   scnt;
    __shared__ int   span_s[9], span_c[10], span_n;

    const int t = blockIdx.x;
    const int tid = threadIdx.x;

    const float tx = tpos[t * 3 + 0];
    const float ty = tpos[t * 3 + 1];
    const float tz = tpos[t * 3 + 2];
    const float tt = tx * tx + ty * ty + tz * tz;
    const float R2 = (float)(0.12 * 0.12);

    // ---- parallel span build ----
    {
        const float RM = 0.121f;
        int lx = max(0, (int)floorf((tx - RM) * (float)GRID));
        int hx = min(GRID - 1, (int)floorf((tx + RM) * (float)GRID));
        int ly = max(0, (int)floorf((ty - RM) * (float)GRID));
        int hy = min(GRID - 1, (int)floorf((ty + RM) * (float)GRID));
        int lz = max(0, (int)floorf((tz - RM) * (float)GRID));
        int hz = min(GRID - 1, (int)floorf((tz + RM) * (float)GRID));
        int nsy = hy - ly + 1;
        int ns  = nsy * (hz - lz + 1);
        if (tid == 0) { scnt = 0; span_n = ns; }
        int len = 0;
        if (tid < ns) {
            int cz = lz + tid / nsy;
            int cy = ly + tid % nsy;
            int cbase = (cz * GRID + cy) * GRID;
            int s0 = g_start[cbase + lx];
            len = g_start[cbase + hx + 1] - s0;
            span_s[tid] = s0;
        }
        if (tid < 32) {
            int v = len;
#pragma unroll
            for (int o = 1; o < 16; o <<= 1) {
                int u = __shfl_up_sync(0xffffffffu, v, o);
                if (tid >= o) v += u;
            }
            if (tid < 9) span_c[tid + 1] = v;
            if (tid == 0) span_c[0] = 0;
        }
    }
    __syncthreads();

    {
        const int ns = span_n;
        const int T = span_c[ns];
        for (int i = tid; i < T; i += 128) {
            int sp = 0;
            while (i >= span_c[sp + 1]) sp++;
            int s = span_s[sp] + (i - span_c[sp]);
            float4 p = g_bp[s];
            float dot = tx * p.x + ty * p.y + tz * p.z;
            float d2 = (tt + p.w) - 2.0f * dot;
            if (d2 <= R2) {
                int c = atomicAdd(&scnt, 1);
                if (c < CMAX) { cd2[c] = d2; cidx[c] = g_bidx[s]; }
            }
        }
    }
    __syncthreads();

    const int C = min(scnt, CMAX);
    const int selCnt = min(C, KN);

    if (C <= KN) {
        if (tid < C) ssel[tid] = cidx[tid];
    } else {
        for (int i = tid; i < C; i += 128) {
            float di = cd2[i];
            int   ii = cidx[i];
            int r = 0;
            for (int k2 = 0; k2 < C; k2++) {
                float dk = cd2[k2];
                r += (int)((dk < di) || (dk == di && cidx[k2] < ii));
            }
            if (r < KN) ssel[r] = cidx[i];
        }
    }
    __syncthreads();

    if (tid < KN) {
        if (tid < selCnt) {
            int j = ssel[tid];
            float4 p = g_spos[j];
            g_nbr[t * KN + tid] = make_float4(p.x - tx, p.y - ty, p.z - tz,
                                              __int_as_float(j));
        } else {
            g_nbr[t * KN + tid] = make_float4(0.f, 0.f, 0.f, __int_as_float(-1));
        }
    }
    if (tid == 0) g_scnt[t] = selCnt;
}

// ---------------------------------------------------------------------------
// GEMM: persistent; per tile 8 targets x 32 nbrs (M=256); split-bf16 mma.sync
// warp grid 4m x 2n, warp tile 64x64: fragment traffic 512 wv/target (was 768)
// ---------------------------------------------------------------------------
__global__ void __launch_bounds__(256) k_gemm(
    const float* __restrict__ W1, const float* __restrict__ W2g,
    const float* __restrict__ b2, float* __restrict__ out)
{
    extern __shared__ char smg[];
    __nv_bfloat16* sBhi = (__nv_bfloat16*)(smg + SM_BHI);
    __nv_bfloat16* sBlo = (__nv_bfloat16*)(smg + SM_BLO);
    __nv_bfloat16* sAhi = (__nv_bfloat16*)(smg + SM_AHI);
    __nv_bfloat16* sAlo = (__nv_bfloat16*)(smg + SM_ALO);
    float*         sW1  = (float*)(smg + SM_W1);      // [3][128]
    float*         sB2  = (float*)(smg + SM_B2);
    float4*        sNbr = (float4*)(smg + SM_NBR);    // 256 entries
    int*           sSc  = (int*)(smg + SM_SC);        // 8 counts

    const int tid  = threadIdx.x;
    const int wid  = tid >> 5;
    const int lane = tid & 31;

    // ---- stage W2 split-bf16 (row-major [k][n]) + W1 positional rows + b2 ----
    for (int i = tid; i < HH * HH; i += 256) {
        int k = i >> 7, n = i & 127;
        float w = W2g[i];
        __nv_bfloat16 hb = __float2bfloat16(w);
        __nv_bfloat16 lb = __float2bfloat16(w - __bfloat162float(hb));
        sBhi[k * LDA + n] = hb;
        sBlo[k * LDA + n] = lb;
    }
    for (int i = tid; i < 3 * HH; i += 256) sW1[i] = W1[64 * HH + i];
    for (int i = tid; i < HH; i += 256)     sB2[i] = b2[i];
    __syncthreads();

    // warp tiling: 4m x 2n; warp tile 64 rows (2 targets) x 64 cols
    const int wm = wid & 3;
    const int wn = wid >> 2;
    const int mA = 64 * wm;
    const int nB = 64 * wn;

    const uint32_t uAhi = smem_u32(sAhi), uAlo = smem_u32(sAlo);
    const uint32_t uBhi = smem_u32(sBhi), uBlo = smem_u32(sBlo);

    // per-thread ldmatrix offsets (bytes)
    const int l15 = lane & 15;
    uint32_t aoff[4];
#pragma unroll
    for (int mt = 0; mt < 4; mt++)
        aoff[mt] = (uint32_t)(((mA + mt * 16 + l15) * LDA + (lane >> 4) * 8) * 2);
    const uint32_t boff  = (uint32_t)((l15 * LDA + nB) * 2);
    const uint32_t kstep = 16 * LDA * 2;

    // per-thread bias registers (cols fixed across tiles)
    const int tid4 = lane & 3;
    const int g4   = lane >> 2;
    float bias0[8], bias1[8];
#pragma unroll
    for (int nt = 0; nt < 8; nt++) {
        int c = nB + nt * 8 + tid4 * 2;
        bias0[nt] = sB2[c];
        bias1[nt] = sB2[c + 1];
    }

    for (int g = blockIdx.x; g < NTILE; g += NBLK_G) {
        const int t0 = g * TPT;

        sNbr[tid] = g_nbr[t0 * KN + tid];          // 256 neighbor entries
        if (tid < TPT) sSc[tid] = g_scnt[t0 + tid];
        __syncthreads();

        const int sc0 = sSc[2 * wm];               // hoist before post-MMA barrier
        const int sc1 = sSc[2 * wm + 1];

        // ---- build A (h1) split-bf16: one row (128 cols) per thread ----
        {
            float4 nb = sNbr[tid];
            int j = __float_as_int(nb.w);
            const float* Srow = g_S + (j >= 0 ? j : 0) * HH;
            __nv_bfloat16* dh = sAhi + tid * LDA;
            __nv_bfloat16* dl = sAlo + tid * LDA;
#pragma unroll 4
            for (int c = 0; c < HH; c += 4) {
                float4 sv = (j >= 0) ? *(const float4*)(Srow + c)
                                     : make_float4(0.f, 0.f, 0.f, 0.f);
                float4 wx = *(const float4*)(sW1 + 0 * HH + c);
                float4 wy = *(const float4*)(sW1 + 1 * HH + c);
                float4 wz = *(const float4*)(sW1 + 2 * HH + c);
                float v[4];
                v[0] = fmaxf(sv.x + nb.x * wx.x + nb.y * wy.x + nb.z * wz.x, 0.f);
                v[1] = fmaxf(sv.y + nb.x * wx.y + nb.y * wy.y + nb.z * wz.y, 0.f);
                v[2] = fmaxf(sv.z + nb.x * wx.z + nb.y * wy.z + nb.z * wz.z, 0.f);
                v[3] = fmaxf(sv.w + nb.x * wx.w + nb.y * wy.w + nb.z * wz.w, 0.f);
                unsigned short hs[4], ls[4];
#pragma unroll
                for (int q = 0; q < 4; q++) {
                    __nv_bfloat16 hb = __float2bfloat16(v[q]);
                    __nv_bfloat16 lb = __float2bfloat16(v[q] - __bfloat162float(hb));
                    hs[q] = __bfloat16_as_ushort(hb);
                    ls[q] = __bfloat16_as_ushort(lb);
                }
                *(uint2*)(dh + c) = make_uint2(((uint32_t)hs[1] << 16) | hs[0],
                                               ((uint32_t)hs[3] << 16) | hs[2]);
                *(uint2*)(dl + c) = make_uint2(((uint32_t)ls[1] << 16) | ls[0],
                                               ((uint32_t)ls[3] << 16) | ls[2]);
            }
        }
        __syncthreads();

        // ---- mma: D = bias + Ah*Bh + Ah*Bl + Al*Bh ----
        float d[4][8][4];
#pragma unroll
        for (int mt = 0; mt < 4; mt++)
#pragma unroll
            for (int nt = 0; nt < 8; nt++) {
                d[mt][nt][0] = bias0[nt];
                d[mt][nt][1] = bias1[nt];
                d[mt][nt][2] = bias0[nt];
                d[mt][nt][3] = bias1[nt];
            }

        uint32_t ah[4][4], al[4][4], bh[2], bl[2];
#pragma unroll
        for (int k0 = 0; k0 < 8; k0++) {
            const uint32_t ka = (uint32_t)(k0 * 32);
#pragma unroll
            for (int mt = 0; mt < 4; mt++) {
                ldsm_x4(ah[mt], uAhi + aoff[mt] + ka);
                ldsm_x4(al[mt], uAlo + aoff[mt] + ka);
            }
            const uint32_t kb = (uint32_t)(k0 * kstep);
#pragma unroll
            for (int nt = 0; nt < 8; nt++) {
                ldsm_x2t(bh, uBhi + boff + kb + nt * 16);
                ldsm_x2t(bl, uBlo + boff + kb + nt * 16);
#pragma unroll
                for (int mt = 0; mt < 4; mt++) {
                    mma_bf16(d[mt][nt], ah[mt], bh);
                    mma_bf16(d[mt][nt], ah[mt], bl);
                    mma_bf16(d[mt][nt], al[mt], bh);
                }
            }
        }
        __syncthreads();   // A reads done before next tile's A build

        // ---- register epilogue: 2 targets per warp ----
        const bool a0 = g4      < sc0, a1 = g4 + 8 < sc0;
        const bool a2 = g4 + 16 < sc0, a3 = g4 + 24 < sc0;
        const bool b0 = g4      < sc1, b1 = g4 + 8 < sc1;
        const bool b2m = g4 + 16 < sc1, b3 = g4 + 24 < sc1;
        const int tO0 = (t0 + 2 * wm) * HH + nB;
        const int tO1 = tO0 + HH;
#pragma unroll
        for (int nt = 0; nt < 8; nt++) {
            float v0 = 0.f, v1 = 0.f, w0 = 0.f, w1 = 0.f;
            if (a0) { v0 = fmaxf(v0, d[0][nt][0]); v1 = fmaxf(v1, d[0][nt][1]); }
            if (a1) { v0 = fmaxf(v0, d[0][nt][2]); v1 = fmaxf(v1, d[0][nt][3]); }
            if (a2) { v0 = fmaxf(v0, d[1][nt][0]); v1 = fmaxf(v1, d[1][nt][1]); }
            if (a3) { v0 = fmaxf(v0, d[1][nt][2]); v1 = fmaxf(v1, d[1][nt][3]); }
            if (b0) { w0 = fmaxf(w0, d[2][nt][0]); w1 = fmaxf(w1, d[2][nt][1]); }
            if (b1) { w0 = fmaxf(w0, d[2][nt][2]); w1 = fmaxf(w1, d[2][nt][3]); }
            if (b2m){ w0 = fmaxf(w0, d[3][nt][0]); w1 = fmaxf(w1, d[3][nt][1]); }
            if (b3) { w0 = fmaxf(w0, d[3][nt][2]); w1 = fmaxf(w1, d[3][nt][3]); }
#pragma unroll
            for (int o = 4; o < 32; o <<= 1) {
                v0 = fmaxf(v0, __shfl_xor_sync(0xffffffffu, v0, o));
                v1 = fmaxf(v1, __shfl_xor_sync(0xffffffffu, v1, o));
                w0 = fmaxf(w0, __shfl_xor_sync(0xffffffffu, w0, o));
                w1 = fmaxf(w1, __shfl_xor_sync(0xffffffffu, w1, o));
            }
            if (lane < 4) {
                *(float2*)(out + tO0 + nt * 8 + lane * 2) = make_float2(v0, v1);
                *(float2*)(out + tO1 + nt * 8 + lane * 2) = make_float2(w0, w1);
            }
        }
    }
}

// ---------------------------------------------------------------------------
__global__ void k_tail(const float* __restrict__ tpos, const int* __restrict__ tb,
                       float* __restrict__ out, int mode)
{
    int i = blockIdx.x * blockDim.x + threadIdx.x;
    const int off = N_TGT * HH;
    if (i < N_TGT * 3) out[off + i] = tpos[i];
    if (mode >= 2 && i < N_TGT) out[off + N_TGT * 3 + i] = (float)tb[i];
}

// ---------------------------------------------------------------------------
extern "C" void kernel_launch(void* const* d_in, const int* in_sizes, int n_in,
                              void* d_out, int out_size)
{
    const float* srcf = (const float*)d_in[0];
    const float* srcp = (const float*)d_in[1];
    const int*   srcb = (const int*)d_in[2];
    const float* tpos = (const float*)d_in[4];
    const int*   tbat = (const int*)d_in[5];
    const float* W1   = (const float*)d_in[6];
    const float* b1   = (const float*)d_in[7];
    const float* W2   = (const float*)d_in[8];
    const float* b2   = (const float*)d_in[9];
    float* out = (float*)d_out;

    cudaFuncSetAttribute(k_gemm, cudaFuncAttributeMaxDynamicSharedMemorySize, SMEM_G);

    k_zero<<<(NCELL + 255) / 256, 256>>>();
    k_pre<<<N_SRC / 4, 128>>>(srcf, srcp, srcb, W1, b1);
    k_scan<<<1, NCELL>>>();
    k_scatter<<<N_SRC / 128, 128>>>();
    k_search<<<N_TGT, 128>>>(tpos);
    k_gemm<<<NBLK_G, 256, SMEM_G>>>(W1, W2, b2, out);

    const int base = N_TGT * HH;
    if (out_size >= base + N_TGT * 3) {
        int mode = (out_size >= base + N_TGT * 3 + N_TGT) ? 2 : 1;
        int tot = N_TGT * 3;
        k_tail<<<(tot + 255) / 256, 256>>>(tpos, tbat, out, mode);
    }
}

// round 11
// speedup vs baseline: 4.0166x; 1.0075x over previous
#include <cuda_runtime.h>
#include <cuda_bf16.h>
#include <cstdint>

#define N_SRC 8192
#define N_TGT 16384
#define DD 64
#define HH 128
#define KN 32
#define CMAX 256
#define GRID 8
#define NCELL (GRID*GRID*GRID)
#define TPT 8                      // targets per GEMM tile (M = 256)
#define NTILE (N_TGT / TPT)        // 2048 tiles
#define NBLK_G 148                 // persistent GEMM blocks (1/SM)

#define LDA 136                    // bf16 leading dim (conflict-free ldmatrix)

// ---------------- device scratch ----------------
static __device__ float  g_S[N_SRC * HH];
static __device__ float4 g_spos[N_SRC];
static __device__ float  g_ss[N_SRC];
static __device__ int    g_cell[N_SRC];
static __device__ int    g_cnt[NCELL];
static __device__ int    g_fill[NCELL];
static __device__ int    g_start[NCELL + 1];
static __device__ float4 g_bp[N_SRC];
static __device__ int    g_bidx[N_SRC];
static __device__ float4 g_nbr[N_TGT * KN];   // (relx, rely, relz, bitcast j or -1)
static __device__ int    g_scnt[N_TGT];

// ---------------- k_gemm smem layout (bytes) ----------------
#define SM_BHI   0                       // 128*136*2 = 34816
#define SM_BLO   34816
#define SM_AHI   69632                   // 256*136*2 = 69632
#define SM_ALO   139264
#define SM_W1    208896                  // 3*128*4 = 1536
#define SM_B2    210432                  // 512
#define SMEM_G   210944

static __device__ __forceinline__ uint32_t smem_u32(const void* p) {
    uint32_t a;
    asm("{ .reg .u64 t; cvta.to.shared.u64 t, %1; cvt.u32.u64 %0, t; }" : "=r"(a) : "l"(p));
    return a;
}

static __device__ __forceinline__ void ldsm_x4(uint32_t* r, uint32_t addr) {
    asm volatile("ldmatrix.sync.aligned.m8n8.x4.shared.b16 {%0,%1,%2,%3}, [%4];"
                 : "=r"(r[0]), "=r"(r[1]), "=r"(r[2]), "=r"(r[3]) : "r"(addr));
}
static __device__ __forceinline__ void ldsm_x2t(uint32_t* r, uint32_t addr) {
    asm volatile("ldmatrix.sync.aligned.m8n8.x2.trans.shared.b16 {%0,%1}, [%2];"
                 : "=r"(r[0]), "=r"(r[1]) : "r"(addr));
}
static __device__ __forceinline__ void mma_bf16(float* d, const uint32_t* a, const uint32_t* b) {
    asm volatile("mma.sync.aligned.m16n8k16.row.col.f32.bf16.bf16.f32 "
                 "{%0,%1,%2,%3}, {%4,%5,%6,%7}, {%8,%9}, {%0,%1,%2,%3};"
                 : "+f"(d[0]), "+f"(d[1]), "+f"(d[2]), "+f"(d[3])
                 : "r"(a[0]), "r"(a[1]), "r"(a[2]), "r"(a[3]), "r"(b[0]), "r"(b[1]));
}

static __device__ __forceinline__ int cell_of(float x, float y, float z) {
    int cx = min(GRID - 1, max(0, (int)floorf(x * (float)GRID)));
    int cy = min(GRID - 1, max(0, (int)floorf(y * (float)GRID)));
    int cz = min(GRID - 1, max(0, (int)floorf(z * (float)GRID)));
    return (cz * GRID + cy) * GRID + cx;
}

// ---------------------------------------------------------------------------
__global__ void k_zero() {
    int i = blockIdx.x * blockDim.x + threadIdx.x;
    if (i < NCELL) { g_cnt[i] = 0; g_fill[i] = 0; }
}

__global__ void __launch_bounds__(128) k_pre(
    const float* __restrict__ srcf, const float* __restrict__ srcp,
    const int* __restrict__ srcb, const float* __restrict__ W1,
    const float* __restrict__ b1)
{
    const int j0 = blockIdx.x * 4;
    const int t = threadIdx.x;
    __shared__ float sx[4][DD];
    for (int i = t; i < 4 * DD; i += 128) sx[i / DD][i % DD] = srcf[j0 * DD + i];
    __syncthreads();
    float a0, a1, a2, a3;
    a0 = a1 = a2 = a3 = b1[t];
#pragma unroll
    for (int d = 0; d < DD; d++) {
        float w = W1[d * HH + t];
        a0 = fmaf(sx[0][d], w, a0);
        a1 = fmaf(sx[1][d], w, a1);
        a2 = fmaf(sx[2][d], w, a2);
        a3 = fmaf(sx[3][d], w, a3);
    }
    g_S[(j0 + 0) * HH + t] = a0;
    g_S[(j0 + 1) * HH + t] = a1;
    g_S[(j0 + 2) * HH + t] = a2;
    g_S[(j0 + 3) * HH + t] = a3;
    if (t < 4) {
        int j = j0 + t;
        float x = srcp[j * 3 + 0], y = srcp[j * 3 + 1], z = srcp[j * 3 + 2];
        g_spos[j] = make_float4(x, y, z, (float)srcb[j]);
        g_ss[j] = x * x + y * y + z * z;
        int c = cell_of(x, y, z);
        g_cell[j] = c;
        atomicAdd(&g_cnt[c], 1);
    }
}

__global__ void __launch_bounds__(NCELL) k_scan() {
    __shared__ int s[NCELL];
    int t = threadIdx.x;
    s[t] = g_cnt[t];
    __syncthreads();
#pragma unroll
    for (int off = 1; off < NCELL; off <<= 1) {
        int v = (t >= off) ? s[t - off] : 0;
        __syncthreads();
        s[t] += v;
        __syncthreads();
    }
    g_start[t + 1] = s[t];
    if (t == 0) g_start[0] = 0;
}

__global__ void __launch_bounds__(128) k_scatter() {
    int j = blockIdx.x * 128 + threadIdx.x;
    if (j >= N_SRC) return;
    int c = g_cell[j];
    int off = atomicAdd(&g_fill[c], 1);
    int dst = g_start[c] + off;
    float4 p = g_spos[j];
    g_bp[dst] = make_float4(p.x, p.y, p.z, g_ss[j]);
    g_bidx[dst] = j;
}

// ---------------------------------------------------------------------------
// search: one block per target; warp-per-span scan + aggregated push
// ---------------------------------------------------------------------------
__global__ void __launch_bounds__(128) k_search(const float* __restrict__ tpos)
{
    __shared__ float cd2[CMAX];
    __shared__ int   cidx[CMAX];
    __shared__ int   ssel[KN];
    __shared__ int   scnt;

    const int t    = blockIdx.x;
    const int tid  = threadIdx.x;
    const int wid  = tid >> 5;
    const int lane = tid & 31;

    const float tx = tpos[t * 3 + 0];
    const float ty = tpos[t * 3 + 1];
    const float tz = tpos[t * 3 + 2];
    const float tt = tx * tx + ty * ty + tz * tz;
    const float R2 = (float)(0.12 * 0.12);

    if (tid == 0) scnt = 0;

    const float RM = 0.121f;
    const int lx = max(0, (int)floorf((tx - RM) * (float)GRID));
    const int hx = min(GRID - 1, (int)floorf((tx + RM) * (float)GRID));
    const int ly = max(0, (int)floorf((ty - RM) * (float)GRID));
    const int hy = min(GRID - 1, (int)floorf((ty + RM) * (float)GRID));
    const int lz = max(0, (int)floorf((tz - RM) * (float)GRID));
    const int hz = min(GRID - 1, (int)floorf((tz + RM) * (float)GRID));
    const int nsy = hy - ly + 1;
    const int ns  = nsy * (hz - lz + 1);
    __syncthreads();               // scnt visible

    for (int sp = wid; sp < ns; sp += 4) {
        const int cz = lz + sp / nsy;
        const int cy = ly + sp % nsy;
        const int cbase = (cz * GRID + cy) * GRID;
        const int s0 = g_start[cbase + lx];
        const int s1 = g_start[cbase + hx + 1];
        for (int s = s0 + lane; s - lane < s1; s += 32) {   // warp-uniform trip
            bool hit = false;
            float d2 = 0.f;
            if (s < s1) {
                float4 p = g_bp[s];
                float dot = tx * p.x + ty * p.y + tz * p.z;
                d2 = (tt + p.w) - 2.0f * dot;
                hit = (d2 <= R2);
            }
            unsigned m = __ballot_sync(0xffffffffu, hit);
            if (m) {
                int leader = __ffs(m) - 1;
                int base = 0;
                if (lane == leader) base = atomicAdd(&scnt, __popc(m));
                base = __shfl_sync(0xffffffffu, base, leader);
                if (hit) {
                    int off = base + __popc(m & ((1u << lane) - 1u));
                    if (off < CMAX) { cd2[off] = d2; cidx[off] = g_bidx[s]; }
                }
            }
        }
    }
    __syncthreads();

    const int C = min(scnt, CMAX);
    const int selCnt = min(C, KN);

    if (C <= KN) {
        if (tid < C) ssel[tid] = cidx[tid];
    } else {
        for (int i = tid; i < C; i += 128) {
            float di = cd2[i];
            int   ii = cidx[i];
            int r = 0;
            for (int k2 = 0; k2 < C; k2++) {
                float dk = cd2[k2];
                r += (int)((dk < di) || (dk == di && cidx[k2] < ii));
            }
            if (r < KN) ssel[r] = cidx[i];
        }
    }
    __syncthreads();

    if (tid < KN) {
        if (tid < selCnt) {
            int j = ssel[tid];
            float4 p = g_spos[j];
            g_nbr[t * KN + tid] = make_float4(p.x - tx, p.y - ty, p.z - tz,
                                              __int_as_float(j));
        } else {
            g_nbr[t * KN + tid] = make_float4(0.f, 0.f, 0.f, __int_as_float(-1));
        }
    }
    if (tid == 0) g_scnt[t] = selCnt;
}

// ---------------------------------------------------------------------------
// GEMM: persistent; per tile 8 targets x 32 nbrs (M=256); split-bf16 mma.sync
// ---------------------------------------------------------------------------
__global__ void __launch_bounds__(256) k_gemm(
    const float* __restrict__ W1, const float* __restrict__ W2g,
    const float* __restrict__ b2, float* __restrict__ out)
{
    extern __shared__ char smg[];
    __nv_bfloat16* sBhi = (__nv_bfloat16*)(smg + SM_BHI);
    __nv_bfloat16* sBlo = (__nv_bfloat16*)(smg + SM_BLO);
    __nv_bfloat16* sAhi = (__nv_bfloat16*)(smg + SM_AHI);
    __nv_bfloat16* sAlo = (__nv_bfloat16*)(smg + SM_ALO);
    float*         sW1  = (float*)(smg + SM_W1);      // [3][128]
    float*         sB2  = (float*)(smg + SM_B2);

    const int tid  = threadIdx.x;
    const int wid  = tid >> 5;
    const int lane = tid & 31;

    // ---- stage W2 split-bf16 (row-major [k][n]) + W1 positional rows + b2 ----
    for (int i = tid; i < HH * HH; i += 256) {
        int k = i >> 7, n = i & 127;
        float w = W2g[i];
        __nv_bfloat16 hb = __float2bfloat16(w);
        __nv_bfloat16 lb = __float2bfloat16(w - __bfloat162float(hb));
        sBhi[k * LDA + n] = hb;
        sBlo[k * LDA + n] = lb;
    }
    for (int i = tid; i < 3 * HH; i += 256) sW1[i] = W1[64 * HH + i];
    for (int i = tid; i < HH; i += 256)     sB2[i] = b2[i];
    __syncthreads();

    // warp tiling: 4m x 2n; warp tile 64 rows (2 targets) x 64 cols
    const int wm = wid & 3;
    const int wn = wid >> 2;
    const int mA = 64 * wm;
    const int nB = 64 * wn;

    const uint32_t uAhi = smem_u32(sAhi), uAlo = smem_u32(sAlo);
    const uint32_t uBhi = smem_u32(sBhi), uBlo = smem_u32(sBlo);

    // per-thread ldmatrix offsets (bytes)
    const int l15 = lane & 15;
    uint32_t aoff[4];
#pragma unroll
    for (int mt = 0; mt < 4; mt++)
        aoff[mt] = (uint32_t)(((mA + mt * 16 + l15) * LDA + (lane >> 4) * 8) * 2);
    const uint32_t boff  = (uint32_t)((l15 * LDA + nB) * 2);
    const uint32_t kstep = 16 * LDA * 2;

    // per-thread bias registers (cols fixed across tiles)
    const int tid4 = lane & 3;
    const int g4   = lane >> 2;
    float bias0[8], bias1[8];
#pragma unroll
    for (int nt = 0; nt < 8; nt++) {
        int c = nB + nt * 8 + tid4 * 2;
        bias0[nt] = sB2[c];
        bias1[nt] = sB2[c + 1];
    }

    for (int g = blockIdx.x; g < NTILE; g += NBLK_G) {
        const int t0 = g * TPT;

        // direct loads (no smem staging / extra barrier needed)
        const float4 nb = g_nbr[t0 * KN + tid];
        const int sc0 = g_scnt[t0 + 2 * wm];
        const int sc1 = g_scnt[t0 + 2 * wm + 1];

        // ---- build A (h1) split-bf16: one row (128 cols) per thread ----
        {
            int j = __float_as_int(nb.w);
            const float* Srow = g_S + (j >= 0 ? j : 0) * HH;
            __nv_bfloat16* dh = sAhi + tid * LDA;
            __nv_bfloat16* dl = sAlo + tid * LDA;
#pragma unroll 4
            for (int c = 0; c < HH; c += 4) {
                float4 sv = (j >= 0) ? *(const float4*)(Srow + c)
                                     : make_float4(0.f, 0.f, 0.f, 0.f);
                float4 wx = *(const float4*)(sW1 + 0 * HH + c);
                float4 wy = *(const float4*)(sW1 + 1 * HH + c);
                float4 wz = *(const float4*)(sW1 + 2 * HH + c);
                float v[4];
                v[0] = fmaxf(sv.x + nb.x * wx.x + nb.y * wy.x + nb.z * wz.x, 0.f);
                v[1] = fmaxf(sv.y + nb.x * wx.y + nb.y * wy.y + nb.z * wz.y, 0.f);
                v[2] = fmaxf(sv.z + nb.x * wx.z + nb.y * wy.z + nb.z * wz.z, 0.f);
                v[3] = fmaxf(sv.w + nb.x * wx.w + nb.y * wy.w + nb.z * wz.w, 0.f);
                unsigned short hs[4], ls[4];
#pragma unroll
                for (int q = 0; q < 4; q++) {
                    __nv_bfloat16 hb = __float2bfloat16(v[q]);
                    __nv_bfloat16 lb = __float2bfloat16(v[q] - __bfloat162float(hb));
                    hs[q] = __bfloat16_as_ushort(hb);
                    ls[q] = __bfloat16_as_ushort(lb);
                }
                *(uint2*)(dh + c) = make_uint2(((uint32_t)hs[1] << 16) | hs[0],
                                               ((uint32_t)hs[3] << 16) | hs[2]);
                *(uint2*)(dl + c) = make_uint2(((uint32_t)ls[1] << 16) | ls[0],
                                               ((uint32_t)ls[3] << 16) | ls[2]);
            }
        }
        __syncthreads();

        // ---- mma: D = bias + Ah*Bh + Ah*Bl + Al*Bh ----
        float d[4][8][4];
#pragma unroll
        for (int mt = 0; mt < 4; mt++)
#pragma unroll
            for (int nt = 0; nt < 8; nt++) {
                d[mt][nt][0] = bias0[nt];
                d[mt][nt][1] = bias1[nt];
                d[mt][nt][2] = bias0[nt];
                d[mt][nt][3] = bias1[nt];
            }

        uint32_t ah[4][4], al[4][4], bh[2], bl[2];
#pragma unroll
        for (int k0 = 0; k0 < 8; k0++) {
            const uint32_t ka = (uint32_t)(k0 * 32);
#pragma unroll
            for (int mt = 0; mt < 4; mt++) {
                ldsm_x4(ah[mt], uAhi + aoff[mt] + ka);
                ldsm_x4(al[mt], uAlo + aoff[mt] + ka);
            }
            const uint32_t kb = (uint32_t)(k0 * kstep);
#pragma unroll
            for (int nt = 0; nt < 8; nt++) {
                ldsm_x2t(bh, uBhi + boff + kb + nt * 16);
                ldsm_x2t(bl, uBlo + boff + kb + nt * 16);
#pragma unroll
                for (int mt = 0; mt < 4; mt++) {
                    mma_bf16(d[mt][nt], ah[mt], bh);
                    mma_bf16(d[mt][nt], ah[mt], bl);
                    mma_bf16(d[mt][nt], al[mt], bh);
                }
            }
        }
        __syncthreads();   // A reads done before next tile's A build

        // ---- register epilogue: 2 targets per warp ----
        const bool a0 = g4      < sc0, a1 = g4 + 8 < sc0;
        const bool a2 = g4 + 16 < sc0, a3 = g4 + 24 < sc0;
        const bool b0 = g4      < sc1, b1 = g4 + 8 < sc1;
        const bool b2m = g4 + 16 < sc1, b3 = g4 + 24 < sc1;
        const int tO0 = (t0 + 2 * wm) * HH + nB;
        const int tO1 = tO0 + HH;
#pragma unroll
        for (int nt = 0; nt < 8; nt++) {
            float v0 = 0.f, v1 = 0.f, w0 = 0.f, w1 = 0.f;
            if (a0) { v0 = fmaxf(v0, d[0][nt][0]); v1 = fmaxf(v1, d[0][nt][1]); }
            if (a1) { v0 = fmaxf(v0, d[0][nt][2]); v1 = fmaxf(v1, d[0][nt][3]); }
            if (a2) { v0 = fmaxf(v0, d[1][nt][0]); v1 = fmaxf(v1, d[1][nt][1]); }
            if (a3) { v0 = fmaxf(v0, d[1][nt][2]); v1 = fmaxf(v1, d[1][nt][3]); }
            if (b0) { w0 = fmaxf(w0, d[2][nt][0]); w1 = fmaxf(w1, d[2][nt][1]); }
            if (b1) { w0 = fmaxf(w0, d[2][nt][2]); w1 = fmaxf(w1, d[2][nt][3]); }
            if (b2m){ w0 = fmaxf(w0, d[3][nt][0]); w1 = fmaxf(w1, d[3][nt][1]); }
            if (b3) { w0 = fmaxf(w0, d[3][nt][2]); w1 = fmaxf(w1, d[3][nt][3]); }
#pragma unroll
            for (int o = 4; o < 32; o <<= 1) {
                v0 = fmaxf(v0, __shfl_xor_sync(0xffffffffu, v0, o));
                v1 = fmaxf(v1, __shfl_xor_sync(0xffffffffu, v1, o));
                w0 = fmaxf(w0, __shfl_xor_sync(0xffffffffu, w0, o));
                w1 = fmaxf(w1, __shfl_xor_sync(0xffffffffu, w1, o));
            }
            if (lane < 4) {
                *(float2*)(out + tO0 + nt * 8 + lane * 2) = make_float2(v0, v1);
                *(float2*)(out + tO1 + nt * 8 + lane * 2) = make_float2(w0, w1);
            }
        }
    }
}

// ---------------------------------------------------------------------------
__global__ void k_tail(const float* __restrict__ tpos, const int* __restrict__ tb,
                       float* __restrict__ out, int mode)
{
    int i = blockIdx.x * blockDim.x + threadIdx.x;
    const int off = N_TGT * HH;
    if (i < N_TGT * 3) out[off + i] = tpos[i];
    if (mode >= 2 && i < N_TGT) out[off + N_TGT * 3 + i] = (float)tb[i];
}

// ---------------------------------------------------------------------------
extern "C" void kernel_launch(void* const* d_in, const int* in_sizes, int n_in,
                              void* d_out, int out_size)
{
    const float* srcf = (const float*)d_in[0];
    const float* srcp = (const float*)d_in[1];
    const int*   srcb = (const int*)d_in[2];
    const float* tpos = (const float*)d_in[4];
    const int*   tbat = (const int*)d_in[5];
    const float* W1   = (const float*)d_in[6];
    const float* b1   = (const float*)d_in[7];
    const float* W2   = (const float*)d_in[8];
    const float* b2   = (const float*)d_in[9];
    float* out = (float*)d_out;

    cudaFuncSetAttribute(k_gemm, cudaFuncAttributeMaxDynamicSharedMemorySize, SMEM_G);

    k_zero<<<(NCELL + 255) / 256, 256>>>();
    k_pre<<<N_SRC / 4, 128>>>(srcf, srcp, srcb, W1, b1);
    k_scan<<<1, NCELL>>>();
    k_scatter<<<N_SRC / 128, 128>>>();
    k_search<<<N_TGT, 128>>>(tpos);
    k_gemm<<<NBLK_G, 256, SMEM_G>>>(W1, W2, b2, out);

    const int base = N_TGT * HH;
    if (out_size >= base + N_TGT * 3) {
        int mode = (out_size >= base + N_TGT * 3 + N_TGT) ? 2 : 1;
        int tot = N_TGT * 3;
        k_tail<<<(tot + 255) / 256, 256>>>(tpos, tbat, out, mode);
    }
}